// round 1
// baseline (speedup 1.0000x reference)
#include <cuda_runtime.h>
#include <math_constants.h>
#include <cfloat>

#define D_MODEL 1024
#define NHEADS  16
#define DHEAD   64
#define BATCH   2
#define SEQ     2048
#define ROWS    (BATCH * SEQ)   // 4096

// Scratch (allocation-free rule: __device__ globals)
__device__ float g_Q[ROWS * D_MODEL];
__device__ float g_K[ROWS * D_MODEL];
__device__ float g_V[ROWS * D_MODEL];
__device__ float g_Z[ROWS * D_MODEL];

// ---------------------------------------------------------------------------
// SGEMM: C[M,N] = A[M,K] * B[N,K]^T   (both row-major, inner dim contiguous)
// Tiles: BM=64, BN=64, BK=16. 256 threads, 4x4 micro-tile per thread.
// ---------------------------------------------------------------------------
#define BM 64
#define BN 64
#define BK 16
#define PAD 68  // 64 + 4 pad, keeps float4 alignment (68*4 % 16 == 0)

__device__ __forceinline__ void gemm_tile_body(
    const float* __restrict__ A, const float* __restrict__ B,
    float* __restrict__ C, int M, int N, int K)
{
    __shared__ float As[BK][PAD];
    __shared__ float Bs[BK][PAD];

    const int tid = threadIdx.x;
    const int tx = tid & 15;        // 0..15
    const int ty = tid >> 4;        // 0..15
    const int m0 = blockIdx.y * BM;
    const int n0 = blockIdx.x * BN;

    const int lr  = tid >> 2;          // 0..63 (load row within tile)
    const int lc4 = (tid & 3) * 4;     // 0,4,8,12 (k offset)

    float acc[4][4] = {};

    for (int k0 = 0; k0 < K; k0 += BK) {
        // load A tile (64 x 16) -> As[k][m]
        float4 av = *(const float4*)(A + (size_t)(m0 + lr) * K + k0 + lc4);
        As[lc4 + 0][lr] = av.x; As[lc4 + 1][lr] = av.y;
        As[lc4 + 2][lr] = av.z; As[lc4 + 3][lr] = av.w;
        // load B tile (64 x 16) -> Bs[k][n]
        float4 bv = *(const float4*)(B + (size_t)(n0 + lr) * K + k0 + lc4);
        Bs[lc4 + 0][lr] = bv.x; Bs[lc4 + 1][lr] = bv.y;
        Bs[lc4 + 2][lr] = bv.z; Bs[lc4 + 3][lr] = bv.w;
        __syncthreads();

        #pragma unroll
        for (int kk = 0; kk < BK; kk++) {
            float4 a = *(const float4*)&As[kk][ty * 4];
            float4 b = *(const float4*)&Bs[kk][tx * 4];
            acc[0][0] = fmaf(a.x, b.x, acc[0][0]);
            acc[0][1] = fmaf(a.x, b.y, acc[0][1]);
            acc[0][2] = fmaf(a.x, b.z, acc[0][2]);
            acc[0][3] = fmaf(a.x, b.w, acc[0][3]);
            acc[1][0] = fmaf(a.y, b.x, acc[1][0]);
            acc[1][1] = fmaf(a.y, b.y, acc[1][1]);
            acc[1][2] = fmaf(a.y, b.z, acc[1][2]);
            acc[1][3] = fmaf(a.y, b.w, acc[1][3]);
            acc[2][0] = fmaf(a.z, b.x, acc[2][0]);
            acc[2][1] = fmaf(a.z, b.y, acc[2][1]);
            acc[2][2] = fmaf(a.z, b.z, acc[2][2]);
            acc[2][3] = fmaf(a.z, b.w, acc[2][3]);
            acc[3][0] = fmaf(a.w, b.x, acc[3][0]);
            acc[3][1] = fmaf(a.w, b.y, acc[3][1]);
            acc[3][2] = fmaf(a.w, b.z, acc[3][2]);
            acc[3][3] = fmaf(a.w, b.w, acc[3][3]);
        }
        __syncthreads();
    }

    #pragma unroll
    for (int i = 0; i < 4; i++) {
        float4 v = make_float4(acc[i][0], acc[i][1], acc[i][2], acc[i][3]);
        *(float4*)(C + (size_t)(m0 + ty * 4 + i) * N + n0 + tx * 4) = v;
    }
}

// QKV projections fused: blockIdx.z selects {Wq->g_Q, Wk->g_K, Wv->g_V}
__global__ void __launch_bounds__(256)
qkv_gemm_kernel(const float* __restrict__ X,
                const float* __restrict__ Wq,
                const float* __restrict__ Wk,
                const float* __restrict__ Wv)
{
    const float* W;
    float* C;
    if (blockIdx.z == 0)      { W = Wq; C = g_Q; }
    else if (blockIdx.z == 1) { W = Wk; C = g_K; }
    else                      { W = Wv; C = g_V; }
    gemm_tile_body(X, W, C, ROWS, D_MODEL, D_MODEL);
}

// Output projection: out = g_Z @ Wo^T
__global__ void __launch_bounds__(256)
out_gemm_kernel(const float* __restrict__ Wo, float* __restrict__ out)
{
    gemm_tile_body(g_Z, Wo, out, ROWS, D_MODEL, D_MODEL);
}

// ---------------------------------------------------------------------------
// Flash attention + exclusive output mod
// grid = (B*H, SEQ/QT); block = QT threads, 1 query per thread
// ---------------------------------------------------------------------------
#define QT 128
#define KT 32

__global__ void __launch_bounds__(QT)
attn_kernel()
{
    __shared__ float Ks[KT][DHEAD];
    __shared__ float Vs[KT][DHEAD];

    const int bh = blockIdx.x;           // 0..31
    const int b  = bh >> 4;
    const int h  = bh & 15;
    const int tid = threadIdx.x;
    const int qrow = b * SEQ + blockIdx.y * QT + tid;
    const float sm_scale = 0.125f;       // 1/sqrt(64)

    // load q (pre-scaled)
    float q[DHEAD];
    {
        const float* Qp = g_Q + (size_t)qrow * D_MODEL + h * DHEAD;
        #pragma unroll
        for (int d = 0; d < DHEAD; d += 4) {
            float4 t = *(const float4*)(Qp + d);
            q[d + 0] = t.x * sm_scale;
            q[d + 1] = t.y * sm_scale;
            q[d + 2] = t.z * sm_scale;
            q[d + 3] = t.w * sm_scale;
        }
    }

    float m = -CUDART_INF_F;
    float l = 0.0f;
    float acc[DHEAD] = {};

    const int lr0 = tid >> 4;            // 0..7
    const int lc4 = (tid & 15) * 4;      // 0..60

    for (int t0 = 0; t0 < SEQ; t0 += KT) {
        // cooperative tile load: KT rows x 64 cols
        #pragma unroll
        for (int i = 0; i < 4; i++) {
            int r = lr0 + i * 8;
            const float* base = (const float*)g_K +
                (size_t)(b * SEQ + t0 + r) * D_MODEL + h * DHEAD + lc4;
            *(float4*)&Ks[r][lc4] = *(const float4*)base;
            const float* baseV = (const float*)g_V +
                (size_t)(b * SEQ + t0 + r) * D_MODEL + h * DHEAD + lc4;
            *(float4*)&Vs[r][lc4] = *(const float4*)baseV;
        }
        __syncthreads();

        float s[KT];
        #pragma unroll
        for (int j = 0; j < KT; j++) {
            float dot = 0.0f;
            #pragma unroll
            for (int d = 0; d < DHEAD; d += 4) {
                float4 kv = *(const float4*)&Ks[j][d];
                dot = fmaf(q[d + 0], kv.x, dot);
                dot = fmaf(q[d + 1], kv.y, dot);
                dot = fmaf(q[d + 2], kv.z, dot);
                dot = fmaf(q[d + 3], kv.w, dot);
            }
            s[j] = dot;
        }

        float mt = m;
        #pragma unroll
        for (int j = 0; j < KT; j++) mt = fmaxf(mt, s[j]);
        float corr = __expf(m - mt);
        m = mt;
        l *= corr;
        #pragma unroll
        for (int d = 0; d < DHEAD; d++) acc[d] *= corr;
        #pragma unroll
        for (int j = 0; j < KT; j++) {
            float p = __expf(s[j] - m);
            l += p;
            s[j] = p;
        }

        #pragma unroll
        for (int j = 0; j < KT; j++) {
            float p = s[j];
            #pragma unroll
            for (int d = 0; d < DHEAD; d += 4) {
                float4 vv = *(const float4*)&Vs[j][d];
                acc[d + 0] = fmaf(p, vv.x, acc[d + 0]);
                acc[d + 1] = fmaf(p, vv.y, acc[d + 1]);
                acc[d + 2] = fmaf(p, vv.z, acc[d + 2]);
                acc[d + 3] = fmaf(p, vv.w, acc[d + 3]);
            }
        }
        __syncthreads();
    }

    // epilogue: Y = acc / l; exclusive output mod against V at the query's own row
    const float inv_l = 1.0f / l;
    float v[DHEAD];
    {
        const float* Vp = g_V + (size_t)qrow * D_MODEL + h * DHEAD;
        #pragma unroll
        for (int d = 0; d < DHEAD; d += 4) {
            float4 t = *(const float4*)(Vp + d);
            v[d + 0] = t.x; v[d + 1] = t.y; v[d + 2] = t.z; v[d + 3] = t.w;
        }
    }

    float v_sq = 0.0f, ydv = 0.0f, y_sq = 0.0f;
    #pragma unroll
    for (int d = 0; d < DHEAD; d++) {
        float y = acc[d] * inv_l;
        acc[d] = y;
        v_sq = fmaf(v[d], v[d], v_sq);
        ydv  = fmaf(y, v[d], ydv);
        y_sq = fmaf(y, y, y_sq);
    }
    float scale = (v_sq > 0.0f) ? (ydv / fmaxf(v_sq, FLT_MIN)) : 0.0f;

    float z_sq = 0.0f;
    float z[DHEAD];
    #pragma unroll
    for (int d = 0; d < DHEAD; d++) {
        float zz = acc[d] - scale * v[d];
        z[d] = zz;
        z_sq = fmaf(zz, zz, z_sq);
    }
    float ref_norm = fmaxf(sqrtf(y_sq), sqrtf(v_sq));
    float tol = FLT_EPSILON * (float)DHEAD * ref_norm;
    bool zero_out = (v_sq > 0.0f) && (sqrtf(z_sq) <= tol);

    float* Zp = g_Z + (size_t)qrow * D_MODEL + h * DHEAD;
    #pragma unroll
    for (int d = 0; d < DHEAD; d += 4) {
        float4 t;
        if (zero_out) { t.x = t.y = t.z = t.w = 0.0f; }
        else { t.x = z[d]; t.y = z[d + 1]; t.z = z[d + 2]; t.w = z[d + 3]; }
        *(float4*)(Zp + d) = t;
    }
}

// ---------------------------------------------------------------------------
extern "C" void kernel_launch(void* const* d_in, const int* in_sizes, int n_in,
                              void* d_out, int out_size)
{
    const float* x  = (const float*)d_in[0];
    const float* Wq = (const float*)d_in[1];
    const float* Wk = (const float*)d_in[2];
    const float* Wv = (const float*)d_in[3];
    const float* Wo = (const float*)d_in[4];
    float* out = (float*)d_out;

    // QKV projections (fused into one launch via grid.z)
    dim3 gqkv(D_MODEL / BN, ROWS / BM, 3);
    qkv_gemm_kernel<<<gqkv, 256>>>(x, Wq, Wk, Wv);

    // flash attention + exclusive output mod
    dim3 gattn(BATCH * NHEADS, SEQ / QT);
    attn_kernel<<<gattn, QT>>>();

    // output projection
    dim3 gout(D_MODEL / BN, ROWS / BM);
    out_gemm_kernel<<<gout, 256>>>(Wo, out);
}

// round 3
// speedup vs baseline: 1.3133x; 1.3133x over previous
#include <cuda_runtime.h>
#include <cuda_bf16.h>
#include <math_constants.h>
#include <cfloat>
#include <cstdint>

#define D_MODEL 1024
#define NHEADS  16
#define DHEAD   64
#define BATCH   2
#define SEQ     2048
#define ROWS    (BATCH * SEQ)   // 4096
#define K3      3072            // 3-slot expanded K

// fp32 scratch
__device__ float g_Q[ROWS * D_MODEL];
__device__ float g_K[ROWS * D_MODEL];
__device__ float g_V[ROWS * D_MODEL];
__device__ float g_Z[ROWS * D_MODEL];
// bf16 3-slot operands
__device__ __nv_bfloat16 g_Xs[ROWS * K3];           // x expanded (A pattern: hi,hi,lo)
__device__ __nv_bfloat16 g_Zs[ROWS * K3];           // Z expanded (A pattern)
__device__ __nv_bfloat16 g_Wqkvs[3 * D_MODEL * K3]; // packed Wq|Wk|Wv (B pattern: hi,lo,hi)
__device__ __nv_bfloat16 g_Wos[D_MODEL * K3];       // Wo (B pattern)

// ---------------------------------------------------------------------------
// helpers (portable: sm_80-class instructions only)
// ---------------------------------------------------------------------------
__device__ __forceinline__ uint32_t smem_u32(const void* p) {
    uint32_t a;
    asm("{ .reg .u64 t; cvta.to.shared.u64 t, %1; cvt.u32.u64 %0, t; }" : "=r"(a) : "l"(p));
    return a;
}
__device__ __forceinline__ void cp_async16(uint32_t dst, const void* src) {
    asm volatile("cp.async.cg.shared.global [%0], [%1], 16;"
                 :: "r"(dst), "l"(src) : "memory");
}
__device__ __forceinline__ void cp_commit() {
    asm volatile("cp.async.commit_group;" ::: "memory");
}
__device__ __forceinline__ void cp_wait2() {
    asm volatile("cp.async.wait_group 2;" ::: "memory");
}
__device__ __forceinline__ uint32_t sw64(uint32_t off) {
    return off ^ ((off >> 3) & 0x30);
}
__device__ __forceinline__ void ldsm4(uint32_t& r0, uint32_t& r1, uint32_t& r2, uint32_t& r3,
                                      uint32_t addr) {
    asm volatile("ldmatrix.sync.aligned.m8n8.x4.shared.b16 {%0,%1,%2,%3}, [%4];"
                 : "=r"(r0), "=r"(r1), "=r"(r2), "=r"(r3) : "r"(addr));
}
__device__ __forceinline__ void mma16816(float* c, const uint32_t* a, const uint32_t* b) {
    asm volatile(
        "mma.sync.aligned.m16n8k16.row.col.f32.bf16.bf16.f32 "
        "{%0,%1,%2,%3}, {%4,%5,%6,%7}, {%8,%9}, {%0,%1,%2,%3};"
        : "+f"(c[0]), "+f"(c[1]), "+f"(c[2]), "+f"(c[3])
        : "r"(a[0]), "r"(a[1]), "r"(a[2]), "r"(a[3]), "r"(b[0]), "r"(b[1]));
}

// ---------------------------------------------------------------------------
// 3-slot conversion kernels
// ---------------------------------------------------------------------------
__global__ void convA_kernel(const float* __restrict__ src_ext, int sel)
{
    const float* src = (sel == 0) ? src_ext : g_Z;
    __nv_bfloat16* dst = (sel == 0) ? g_Xs : g_Zs;
    int i = blockIdx.x * blockDim.x + threadIdx.x;
    if (i >= ROWS * D_MODEL) return;
    float x = src[i];
    __nv_bfloat16 h = __float2bfloat16_rn(x);
    __nv_bfloat16 l = __float2bfloat16_rn(x - __bfloat162float(h));
    size_t o = (size_t)i * 3;
    dst[o] = h; dst[o + 1] = h; dst[o + 2] = l;
}

__global__ void convB_kernel(const float* __restrict__ src, int which)
{
    __nv_bfloat16* dst = (which < 3) ? (g_Wqkvs + (size_t)which * D_MODEL * K3) : g_Wos;
    int i = blockIdx.x * blockDim.x + threadIdx.x;
    if (i >= D_MODEL * D_MODEL) return;
    float x = src[i];
    __nv_bfloat16 h = __float2bfloat16_rn(x);
    __nv_bfloat16 l = __float2bfloat16_rn(x - __bfloat162float(h));
    size_t o = (size_t)i * 3;
    dst[o] = h; dst[o + 1] = l; dst[o + 2] = h;
}

// ---------------------------------------------------------------------------
// HMMA bf16 GEMM: C[M, N] = A[M, K3] * B[N, K3]^T  (both K-major)
// CTA tile 256x128, BK=32, 512 threads (warp grid 4m x 4n, warp tile 64x32).
// 3-stage cp.async pipeline, SW64 swizzle, ldmatrix + mma.sync.m16n8k16.
// mode 0: A=g_Xs, B=g_Wqkvs (N=3072), epilogue scatters to g_Q/g_K/g_V.
// mode 1: A=g_Zs, B=g_Wos (N=1024), epilogue writes outp.
// ---------------------------------------------------------------------------
#define BMg 256
#define BNg 128
#define NCHUNK (K3 / 32)            // 96
#define STAGE_A (BMg * 64)          // 16384 B
#define STAGE_B (BNg * 64)          // 8192 B
#define STAGE (STAGE_A + STAGE_B)   // 24576 B
#define GSMEM (3 * STAGE)           // 73728 B

__global__ void __launch_bounds__(512, 1)
gemm3s_kernel(float* __restrict__ outp, int mode)
{
    extern __shared__ char smem[];
    const uint32_t sbase = smem_u32(smem);
    const int tid = threadIdx.x;
    const int wid = tid >> 5;
    const int lane = tid & 31;
    const int wm = wid >> 2;        // 0..3 (64-row slice)
    const int wn = wid & 3;         // 0..3 (32-col slice)
    const int m0 = blockIdx.y * BMg;
    const int n0 = blockIdx.x * BNg;

    const __nv_bfloat16* A = (mode == 0) ? g_Xs : g_Zs;
    const __nv_bfloat16* B = (mode == 0) ? g_Wqkvs : g_Wos;
    const __nv_bfloat16* Abase = A + (size_t)m0 * K3;
    const __nv_bfloat16* Bbase = B + (size_t)n0 * K3;

    // ---- fill: 1024 A granules + 512 B granules (16B each), 3 per thread
    auto fill = [&](int stage, int chunk) {
        uint32_t base = sbase + stage * STAGE;
        const __nv_bfloat16* Ac = Abase + chunk * 32;
        const __nv_bfloat16* Bc = Bbase + chunk * 32;
        #pragma unroll
        for (int i = 0; i < 3; i++) {
            int gidx = i * 512 + tid;
            if (gidx < 1024) {
                int row = gidx >> 2, g = gidx & 3;
                uint32_t off = (uint32_t)(row * 64 + g * 16);
                cp_async16(base + sw64(off), Ac + (size_t)row * K3 + g * 8);
            } else {
                int bi = gidx - 1024;
                int row = bi >> 2, g = bi & 3;
                uint32_t off = (uint32_t)(row * 64 + g * 16);
                cp_async16(base + STAGE_A + sw64(off), Bc + (size_t)row * K3 + g * 8);
            }
        }
    };

    float acc[4][4][4] = {};   // [m-tile][n-tile][frag]

    fill(0, 0); cp_commit();
    fill(1, 1); cp_commit();

    for (int c = 0; c < NCHUNK; c++) {
        if (c + 2 < NCHUNK) fill((c + 2) % 3, c + 2);
        cp_commit();
        cp_wait2();
        __syncthreads();

        uint32_t abase = sbase + (c % 3) * STAGE;
        uint32_t bbase = abase + STAGE_A;

        #pragma unroll
        for (int ks = 0; ks < 2; ks++) {
            const int kb = ks * 32;   // byte offset of this k16 within the 64B row
            uint32_t af[4][4];
            #pragma unroll
            for (int mt = 0; mt < 4; mt++) {
                int row = wm * 64 + mt * 16 + (lane & 15);
                int col = kb + ((lane >> 4) * 16);
                ldsm4(af[mt][0], af[mt][1], af[mt][2], af[mt][3],
                      abase + sw64((uint32_t)(row * 64 + col)));
            }
            uint32_t bf[4][2];
            #pragma unroll
            for (int bt = 0; bt < 2; bt++) {
                int row = wn * 32 + bt * 16 + (lane & 7) + ((lane >> 4) & 1) * 8;
                int col = kb + (((lane >> 3) & 1) * 16);
                ldsm4(bf[2 * bt][0], bf[2 * bt][1], bf[2 * bt + 1][0], bf[2 * bt + 1][1],
                      bbase + sw64((uint32_t)(row * 64 + col)));
            }
            #pragma unroll
            for (int mt = 0; mt < 4; mt++)
                #pragma unroll
                for (int nt = 0; nt < 4; nt++)
                    mma16816(acc[mt][nt], af[mt], bf[nt]);
        }
        __syncthreads();
    }

    // ---- epilogue
    const int gid = lane >> 2;
    const int tid2 = lane & 3;
    #pragma unroll
    for (int mt = 0; mt < 4; mt++) {
        int row0 = m0 + wm * 64 + mt * 16 + gid;
        #pragma unroll
        for (int nt = 0; nt < 4; nt++) {
            int ncol = n0 + wn * 32 + nt * 8 + tid2 * 2;
            float* tgt;
            int col;
            if (mode == 0) {
                tgt = (ncol < 1024) ? g_Q : ((ncol < 2048) ? g_K : g_V);
                col = ncol & 1023;
            } else {
                tgt = outp;
                col = ncol;
            }
            *(float2*)(tgt + (size_t)row0 * 1024 + col) =
                make_float2(acc[mt][nt][0], acc[mt][nt][1]);
            *(float2*)(tgt + (size_t)(row0 + 8) * 1024 + col) =
                make_float2(acc[mt][nt][2], acc[mt][nt][3]);
        }
    }
}

// ---------------------------------------------------------------------------
// Flash attention + exclusive output mod (fp32, unchanged from R1)
// ---------------------------------------------------------------------------
#define QT 128
#define KT 32

__global__ void __launch_bounds__(QT)
attn_kernel()
{
    __shared__ float Ks[KT][DHEAD];
    __shared__ float Vs[KT][DHEAD];

    const int bh = blockIdx.x;
    const int b  = bh >> 4;
    const int h  = bh & 15;
    const int tid = threadIdx.x;
    const int qrow = b * SEQ + blockIdx.y * QT + tid;
    const float sm_scale = 0.125f;

    float q[DHEAD];
    {
        const float* Qp = g_Q + (size_t)qrow * D_MODEL + h * DHEAD;
        #pragma unroll
        for (int d = 0; d < DHEAD; d += 4) {
            float4 t = *(const float4*)(Qp + d);
            q[d + 0] = t.x * sm_scale;
            q[d + 1] = t.y * sm_scale;
            q[d + 2] = t.z * sm_scale;
            q[d + 3] = t.w * sm_scale;
        }
    }

    float m = -CUDART_INF_F;
    float l = 0.0f;
    float acc[DHEAD] = {};

    const int lr0 = tid >> 4;
    const int lc4 = (tid & 15) * 4;

    for (int t0 = 0; t0 < SEQ; t0 += KT) {
        #pragma unroll
        for (int i = 0; i < 4; i++) {
            int r = lr0 + i * 8;
            const float* base = g_K + (size_t)(b * SEQ + t0 + r) * D_MODEL + h * DHEAD + lc4;
            *(float4*)&Ks[r][lc4] = *(const float4*)base;
            const float* baseV = g_V + (size_t)(b * SEQ + t0 + r) * D_MODEL + h * DHEAD + lc4;
            *(float4*)&Vs[r][lc4] = *(const float4*)baseV;
        }
        __syncthreads();

        float s[KT];
        #pragma unroll
        for (int j = 0; j < KT; j++) {
            float dot = 0.0f;
            #pragma unroll
            for (int d = 0; d < DHEAD; d += 4) {
                float4 kv = *(const float4*)&Ks[j][d];
                dot = fmaf(q[d + 0], kv.x, dot);
                dot = fmaf(q[d + 1], kv.y, dot);
                dot = fmaf(q[d + 2], kv.z, dot);
                dot = fmaf(q[d + 3], kv.w, dot);
            }
            s[j] = dot;
        }

        float mt = m;
        #pragma unroll
        for (int j = 0; j < KT; j++) mt = fmaxf(mt, s[j]);
        float corr = __expf(m - mt);
        m = mt;
        l *= corr;
        #pragma unroll
        for (int d = 0; d < DHEAD; d++) acc[d] *= corr;
        #pragma unroll
        for (int j = 0; j < KT; j++) {
            float p = __expf(s[j] - m);
            l += p;
            s[j] = p;
        }

        #pragma unroll
        for (int j = 0; j < KT; j++) {
            float p = s[j];
            #pragma unroll
            for (int d = 0; d < DHEAD; d += 4) {
                float4 vv = *(const float4*)&Vs[j][d];
                acc[d + 0] = fmaf(p, vv.x, acc[d + 0]);
                acc[d + 1] = fmaf(p, vv.y, acc[d + 1]);
                acc[d + 2] = fmaf(p, vv.z, acc[d + 2]);
                acc[d + 3] = fmaf(p, vv.w, acc[d + 3]);
            }
        }
        __syncthreads();
    }

    const float inv_l = 1.0f / l;
    float v[DHEAD];
    {
        const float* Vp = g_V + (size_t)qrow * D_MODEL + h * DHEAD;
        #pragma unroll
        for (int d = 0; d < DHEAD; d += 4) {
            float4 t = *(const float4*)(Vp + d);
            v[d + 0] = t.x; v[d + 1] = t.y; v[d + 2] = t.z; v[d + 3] = t.w;
        }
    }

    float v_sq = 0.0f, ydv = 0.0f, y_sq = 0.0f;
    #pragma unroll
    for (int d = 0; d < DHEAD; d++) {
        float y = acc[d] * inv_l;
        acc[d] = y;
        v_sq = fmaf(v[d], v[d], v_sq);
        ydv  = fmaf(y, v[d], ydv);
        y_sq = fmaf(y, y, y_sq);
    }
    float scale = (v_sq > 0.0f) ? (ydv / fmaxf(v_sq, FLT_MIN)) : 0.0f;

    float z_sq = 0.0f;
    float z[DHEAD];
    #pragma unroll
    for (int d = 0; d < DHEAD; d++) {
        float zz = acc[d] - scale * v[d];
        z[d] = zz;
        z_sq = fmaf(zz, zz, z_sq);
    }
    float ref_norm = fmaxf(sqrtf(y_sq), sqrtf(v_sq));
    float tol = FLT_EPSILON * (float)DHEAD * ref_norm;
    bool zero_out = (v_sq > 0.0f) && (sqrtf(z_sq) <= tol);

    float* Zp = g_Z + (size_t)qrow * D_MODEL + h * DHEAD;
    #pragma unroll
    for (int d = 0; d < DHEAD; d += 4) {
        float4 t;
        if (zero_out) { t.x = t.y = t.z = t.w = 0.0f; }
        else { t.x = z[d]; t.y = z[d + 1]; t.z = z[d + 2]; t.w = z[d + 3]; }
        *(float4*)(Zp + d) = t;
    }
}

// ---------------------------------------------------------------------------
extern "C" void kernel_launch(void* const* d_in, const int* in_sizes, int n_in,
                              void* d_out, int out_size)
{
    const float* x  = (const float*)d_in[0];
    const float* Wq = (const float*)d_in[1];
    const float* Wk = (const float*)d_in[2];
    const float* Wv = (const float*)d_in[3];
    const float* Wo = (const float*)d_in[4];
    float* out = (float*)d_out;

    cudaFuncSetAttribute(gemm3s_kernel, cudaFuncAttributeMaxDynamicSharedMemorySize, GSMEM);

    // 3-slot conversions
    convA_kernel<<<(ROWS * D_MODEL + 255) / 256, 256>>>(x, 0);
    convB_kernel<<<(D_MODEL * D_MODEL + 255) / 256, 256>>>(Wq, 0);
    convB_kernel<<<(D_MODEL * D_MODEL + 255) / 256, 256>>>(Wk, 1);
    convB_kernel<<<(D_MODEL * D_MODEL + 255) / 256, 256>>>(Wv, 2);
    convB_kernel<<<(D_MODEL * D_MODEL + 255) / 256, 256>>>(Wo, 3);

    // fused QKV projection: C[4096, 3072] scattered into g_Q/g_K/g_V
    dim3 gqkv(3 * D_MODEL / BNg, ROWS / BMg);   // (24, 16)
    gemm3s_kernel<<<gqkv, 512, GSMEM>>>(nullptr, 0);

    // flash attention + exclusive output mod
    dim3 gattn(BATCH * NHEADS, SEQ / QT);
    attn_kernel<<<gattn, QT>>>();

    // Z -> 3-slot, then output projection
    convA_kernel<<<(ROWS * D_MODEL + 255) / 256, 256>>>(nullptr, 1);
    dim3 gout(D_MODEL / BNg, ROWS / BMg);       // (8, 16)
    gemm3s_kernel<<<gout, 512, GSMEM>>>(out, 1);
}

// round 5
// speedup vs baseline: 2.8817x; 2.1943x over previous
#include <cuda_runtime.h>
#include <cuda_bf16.h>
#include <math_constants.h>
#include <cfloat>
#include <cstdint>

#define D_MODEL 1024
#define NHEADS  16
#define DHEAD   64
#define BATCH   2
#define SEQ     2048
#define ROWS    (BATCH * SEQ)   // 4096
#define K3      3072            // 3-slot expanded K
#define NBH     (BATCH * NHEADS)

// fp32 scratch
__device__ float g_Q[ROWS * D_MODEL];
__device__ float g_K[ROWS * D_MODEL];
__device__ float g_V[ROWS * D_MODEL];
__device__ float g_Z[ROWS * D_MODEL];
// bf16 3-slot GEMM operands
__device__ __nv_bfloat16 g_Xs[ROWS * K3];
__device__ __nv_bfloat16 g_Zs[ROWS * K3];
__device__ __nv_bfloat16 g_Wqkvs[3 * D_MODEL * K3];
__device__ __nv_bfloat16 g_Wos[D_MODEL * K3];
// attention operands (per-head layouts)
__device__ __nv_bfloat16 g_Qs3[NBH * SEQ * 192];   // (qh,qh,ql), scaled by 0.125*log2e
__device__ __nv_bfloat16 g_Ks3[NBH * SEQ * 192];   // (kh,kl,kh)
__device__ __nv_bfloat16 g_Vh[NBH * SEQ * DHEAD];  // V hi
__device__ __nv_bfloat16 g_Vl[NBH * SEQ * DHEAD];  // V lo

// ---------------------------------------------------------------------------
// helpers
// ---------------------------------------------------------------------------
__device__ __forceinline__ uint32_t smem_u32(const void* p) {
    uint32_t a;
    asm("{ .reg .u64 t; cvta.to.shared.u64 t, %1; cvt.u32.u64 %0, t; }" : "=r"(a) : "l"(p));
    return a;
}
__device__ __forceinline__ void cp_async16(uint32_t dst, const void* src) {
    asm volatile("cp.async.cg.shared.global [%0], [%1], 16;" :: "r"(dst), "l"(src) : "memory");
}
__device__ __forceinline__ void cp_commit() {
    asm volatile("cp.async.commit_group;" ::: "memory");
}
__device__ __forceinline__ void cp_wait1() {
    asm volatile("cp.async.wait_group 1;" ::: "memory");
}
__device__ __forceinline__ void cp_wait2() {
    asm volatile("cp.async.wait_group 2;" ::: "memory");
}
__device__ __forceinline__ uint32_t sw64(uint32_t off)  { return off ^ ((off >> 3) & 0x30); }
__device__ __forceinline__ uint32_t sw128(uint32_t off) { return off ^ ((off >> 3) & 0x70); }
__device__ __forceinline__ void ldsm4(uint32_t& r0, uint32_t& r1, uint32_t& r2, uint32_t& r3,
                                      uint32_t addr) {
    asm volatile("ldmatrix.sync.aligned.m8n8.x4.shared.b16 {%0,%1,%2,%3}, [%4];"
                 : "=r"(r0), "=r"(r1), "=r"(r2), "=r"(r3) : "r"(addr));
}
__device__ __forceinline__ void ldsm4t(uint32_t& r0, uint32_t& r1, uint32_t& r2, uint32_t& r3,
                                       uint32_t addr) {
    asm volatile("ldmatrix.sync.aligned.m8n8.x4.trans.shared.b16 {%0,%1,%2,%3}, [%4];"
                 : "=r"(r0), "=r"(r1), "=r"(r2), "=r"(r3) : "r"(addr));
}
__device__ __forceinline__ void mma16816(float* c, const uint32_t* a, const uint32_t* b) {
    asm volatile(
        "mma.sync.aligned.m16n8k16.row.col.f32.bf16.bf16.f32 "
        "{%0,%1,%2,%3}, {%4,%5,%6,%7}, {%8,%9}, {%0,%1,%2,%3};"
        : "+f"(c[0]), "+f"(c[1]), "+f"(c[2]), "+f"(c[3])
        : "r"(a[0]), "r"(a[1]), "r"(a[2]), "r"(a[3]), "r"(b[0]), "r"(b[1]));
}
__device__ __forceinline__ float ex2f(float x) {
    float y; asm("ex2.approx.ftz.f32 %0, %1;" : "=f"(y) : "f"(x)); return y;
}
__device__ __forceinline__ uint32_t packbf(float hi, float lo) {
    uint32_t r; asm("cvt.rn.bf16x2.f32 %0, %1, %2;" : "=r"(r) : "f"(hi), "f"(lo)); return r;
}
__device__ __forceinline__ float qsum(float v) {
    v += __shfl_xor_sync(0xffffffffu, v, 1);
    v += __shfl_xor_sync(0xffffffffu, v, 2);
    return v;
}
__device__ __forceinline__ float qmax(float v) {
    v = fmaxf(v, __shfl_xor_sync(0xffffffffu, v, 1));
    v = fmaxf(v, __shfl_xor_sync(0xffffffffu, v, 2));
    return v;
}

// ---------------------------------------------------------------------------
// conversion kernels
// ---------------------------------------------------------------------------
__global__ void convA_kernel(const float* __restrict__ src_ext, int sel)
{
    const float* src = (sel == 0) ? src_ext : g_Z;
    __nv_bfloat16* dst = (sel == 0) ? g_Xs : g_Zs;
    int i = blockIdx.x * blockDim.x + threadIdx.x;
    if (i >= ROWS * D_MODEL) return;
    float x = src[i];
    __nv_bfloat16 h = __float2bfloat16_rn(x);
    __nv_bfloat16 l = __float2bfloat16_rn(x - __bfloat162float(h));
    size_t o = (size_t)i * 3;
    dst[o] = h; dst[o + 1] = h; dst[o + 2] = l;
}

__global__ void convB_kernel(const float* __restrict__ src, int which)
{
    __nv_bfloat16* dst = (which < 3) ? (g_Wqkvs + (size_t)which * D_MODEL * K3) : g_Wos;
    int i = blockIdx.x * blockDim.x + threadIdx.x;
    if (i >= D_MODEL * D_MODEL) return;
    float x = src[i];
    __nv_bfloat16 h = __float2bfloat16_rn(x);
    __nv_bfloat16 l = __float2bfloat16_rn(x - __bfloat162float(h));
    size_t o = (size_t)i * 3;
    dst[o] = h; dst[o + 1] = l; dst[o + 2] = h;
}

// Q/K -> 3-slot per-head layout; V -> hi/lo per-head layout
__global__ void convAttn_kernel()
{
    int i = blockIdx.x * blockDim.x + threadIdx.x;
    if (i >= ROWS * D_MODEL) return;
    int row = i >> 10, c = i & 1023;
    int b = row >> 11, t = row & 2047;
    int hh = c >> 6, d = c & 63;
    size_t bht = (size_t)(b * NHEADS + hh) * SEQ + t;
    size_t o3 = bht * 192 + d * 3;
    {
        float q = g_Q[i] * 0.18033688011112042f;   // 0.125 * log2(e)
        __nv_bfloat16 h = __float2bfloat16_rn(q);
        __nv_bfloat16 l = __float2bfloat16_rn(q - __bfloat162float(h));
        g_Qs3[o3] = h; g_Qs3[o3 + 1] = h; g_Qs3[o3 + 2] = l;
    }
    {
        float k = g_K[i];
        __nv_bfloat16 h = __float2bfloat16_rn(k);
        __nv_bfloat16 l = __float2bfloat16_rn(k - __bfloat162float(h));
        g_Ks3[o3] = h; g_Ks3[o3 + 1] = l; g_Ks3[o3 + 2] = h;
    }
    {
        float v = g_V[i];
        __nv_bfloat16 h = __float2bfloat16_rn(v);
        __nv_bfloat16 l = __float2bfloat16_rn(v - __bfloat162float(h));
        size_t ov = bht * DHEAD + d;
        g_Vh[ov] = h; g_Vl[ov] = l;
    }
}

// ---------------------------------------------------------------------------
// HMMA bf16 GEMM (unchanged from R3)
// ---------------------------------------------------------------------------
#define BMg 256
#define BNg 128
#define NCHUNK (K3 / 32)
#define STAGE_A (BMg * 64)
#define STAGE_B (BNg * 64)
#define STAGE (STAGE_A + STAGE_B)
#define GSMEM (3 * STAGE)

__global__ void __launch_bounds__(512, 1)
gemm3s_kernel(float* __restrict__ outp, int mode)
{
    extern __shared__ char smem[];
    const uint32_t sbase = smem_u32(smem);
    const int tid = threadIdx.x;
    const int wid = tid >> 5;
    const int lane = tid & 31;
    const int wm = wid >> 2;
    const int wn = wid & 3;
    const int m0 = blockIdx.y * BMg;
    const int n0 = blockIdx.x * BNg;

    const __nv_bfloat16* A = (mode == 0) ? g_Xs : g_Zs;
    const __nv_bfloat16* B = (mode == 0) ? g_Wqkvs : g_Wos;
    const __nv_bfloat16* Abase = A + (size_t)m0 * K3;
    const __nv_bfloat16* Bbase = B + (size_t)n0 * K3;

    auto fill = [&](int stage, int chunk) {
        uint32_t base = sbase + stage * STAGE;
        const __nv_bfloat16* Ac = Abase + chunk * 32;
        const __nv_bfloat16* Bc = Bbase + chunk * 32;
        #pragma unroll
        for (int i = 0; i < 3; i++) {
            int gidx = i * 512 + tid;
            if (gidx < 1024) {
                int row = gidx >> 2, g = gidx & 3;
                uint32_t off = (uint32_t)(row * 64 + g * 16);
                cp_async16(base + sw64(off), Ac + (size_t)row * K3 + g * 8);
            } else {
                int bi = gidx - 1024;
                int row = bi >> 2, g = bi & 3;
                uint32_t off = (uint32_t)(row * 64 + g * 16);
                cp_async16(base + STAGE_A + sw64(off), Bc + (size_t)row * K3 + g * 8);
            }
        }
    };

    float acc[4][4][4] = {};

    fill(0, 0); cp_commit();
    fill(1, 1); cp_commit();

    for (int c = 0; c < NCHUNK; c++) {
        if (c + 2 < NCHUNK) fill((c + 2) % 3, c + 2);
        cp_commit();
        cp_wait2();
        __syncthreads();

        uint32_t abase = sbase + (c % 3) * STAGE;
        uint32_t bbase = abase + STAGE_A;

        #pragma unroll
        for (int ks = 0; ks < 2; ks++) {
            const int kb = ks * 32;
            uint32_t af[4][4];
            #pragma unroll
            for (int mt = 0; mt < 4; mt++) {
                int row = wm * 64 + mt * 16 + (lane & 15);
                int col = kb + ((lane >> 4) * 16);
                ldsm4(af[mt][0], af[mt][1], af[mt][2], af[mt][3],
                      abase + sw64((uint32_t)(row * 64 + col)));
            }
            uint32_t bf[4][2];
            #pragma unroll
            for (int bt = 0; bt < 2; bt++) {
                int row = wn * 32 + bt * 16 + (lane & 7) + ((lane >> 4) & 1) * 8;
                int col = kb + (((lane >> 3) & 1) * 16);
                ldsm4(bf[2 * bt][0], bf[2 * bt][1], bf[2 * bt + 1][0], bf[2 * bt + 1][1],
                      bbase + sw64((uint32_t)(row * 64 + col)));
            }
            #pragma unroll
            for (int mt = 0; mt < 4; mt++)
                #pragma unroll
                for (int nt = 0; nt < 4; nt++)
                    mma16816(acc[mt][nt], af[mt], bf[nt]);
        }
        __syncthreads();
    }

    const int gid = lane >> 2;
    const int tid2 = lane & 3;
    #pragma unroll
    for (int mt = 0; mt < 4; mt++) {
        int row0 = m0 + wm * 64 + mt * 16 + gid;
        #pragma unroll
        for (int nt = 0; nt < 4; nt++) {
            int ncol = n0 + wn * 32 + nt * 8 + tid2 * 2;
            float* tgt;
            int col;
            if (mode == 0) {
                tgt = (ncol < 1024) ? g_Q : ((ncol < 2048) ? g_K : g_V);
                col = ncol & 1023;
            } else {
                tgt = outp;
                col = ncol;
            }
            *(float2*)(tgt + (size_t)row0 * 1024 + col) =
                make_float2(acc[mt][nt][0], acc[mt][nt][1]);
            *(float2*)(tgt + (size_t)(row0 + 8) * 1024 + col) =
                make_float2(acc[mt][nt][2], acc[mt][nt][3]);
        }
    }
}

// ---------------------------------------------------------------------------
// Tensor-core flash attention + exclusive output mod
// CTA: 256 q rows (16 warps, 16 rows each), KV tile 64, double-buffered.
// ---------------------------------------------------------------------------
#define AQ_PANEL 32768
#define A_STAGE  40960
#define ASMEM    (3 * AQ_PANEL + 2 * A_STAGE)   // 180224
#define NKV      (SEQ / 64)                     // 32

__global__ void __launch_bounds__(512, 1)
attn_mma_kernel()
{
    extern __shared__ char smem[];
    const uint32_t sb = smem_u32(smem);
    const uint32_t sQ = sb;
    const int tid = threadIdx.x;
    const int wid = tid >> 5;
    const int lane = tid & 31;
    const int bh = blockIdx.x;
    const int q0 = blockIdx.y * 256;
    const int b_ = bh >> 4, h_ = bh & 15;

    const __nv_bfloat16* Qsrc = g_Qs3 + ((size_t)bh * SEQ + q0) * 192;
    const __nv_bfloat16* Ksrc = g_Ks3 + (size_t)bh * SEQ * 192;
    const __nv_bfloat16* Vhsrc = g_Vh + (size_t)bh * SEQ * DHEAD;
    const __nv_bfloat16* Vlsrc = g_Vl + (size_t)bh * SEQ * DHEAD;

    // ---- Q fill: 256 rows x 384B = 6144 granules
    {
        #pragma unroll
        for (int i = 0; i < 12; i++) {
            int g = i * 512 + tid;
            int row = g / 24, w = g % 24;
            uint32_t addr = sQ + (w >> 3) * AQ_PANEL + sw128((uint32_t)(row * 128 + (w & 7) * 16));
            cp_async16(addr, Qsrc + (size_t)row * 192 + w * 8);
        }
    }
    // ---- KV fill
    auto fillKV = [&](int stage, int kt) {
        uint32_t base = sb + 3 * AQ_PANEL + stage * A_STAGE;
        int t0 = kt * 64;
        #pragma unroll
        for (int i = 0; i < 5; i++) {
            int g = i * 512 + tid;
            if (g < 1536) {
                int row = g / 24, w = g % 24;
                uint32_t addr = base + (w >> 3) * 8192 + sw128((uint32_t)(row * 128 + (w & 7) * 16));
                cp_async16(addr, Ksrc + (size_t)(t0 + row) * 192 + w * 8);
            } else if (g < 2048) {
                int v = g - 1536;
                int row = v >> 3, w = v & 7;
                uint32_t addr = base + 24576 + sw128((uint32_t)(row * 128 + w * 16));
                cp_async16(addr, Vhsrc + (size_t)(t0 + row) * DHEAD + w * 8);
            } else {
                int v = g - 2048;
                int row = v >> 3, w = v & 7;
                uint32_t addr = base + 32768 + sw128((uint32_t)(row * 128 + w * 16));
                cp_async16(addr, Vlsrc + (size_t)(t0 + row) * DHEAD + w * 8);
            }
        }
    };

    cp_commit();
    fillKV(0, 0); cp_commit();
    fillKV(1, 1); cp_commit();

    float accO[8][4] = {};
    float m0 = -CUDART_INF_F, m1 = -CUDART_INF_F;
    float l0 = 0.0f, l1 = 0.0f;

    cp_wait1(); __syncthreads();

    for (int kt = 0; kt < NKV; kt++) {
        const uint32_t kb = sb + 3 * AQ_PANEL + (kt & 1) * A_STAGE;

        // ---- S = Q'K'^T
        float accS[8][4] = {};
        const int arow = wid * 16 + (lane & 15);
        #pragma unroll
        for (int s = 0; s < 12; s++) {
            uint32_t af[4];
            ldsm4(af[0], af[1], af[2], af[3],
                  sQ + (s >> 2) * AQ_PANEL +
                  sw128((uint32_t)(arow * 128 + (s & 3) * 32 + (lane >> 4) * 16)));
            #pragma unroll
            for (int nb = 0; nb < 4; nb++) {
                int row = nb * 16 + (lane & 7) + ((lane >> 4) & 1) * 8;
                int off = (s & 3) * 32 + ((lane >> 3) & 1) * 16;
                uint32_t bfr[4];
                ldsm4(bfr[0], bfr[1], bfr[2], bfr[3],
                      kb + (s >> 2) * 8192 + sw128((uint32_t)(row * 128 + off)));
                mma16816(accS[2 * nb], af, &bfr[0]);
                mma16816(accS[2 * nb + 1], af, &bfr[2]);
            }
        }

        // ---- online softmax (base-2)
        float mx0 = -CUDART_INF_F, mx1 = -CUDART_INF_F;
        #pragma unroll
        for (int nt = 0; nt < 8; nt++) {
            mx0 = fmaxf(mx0, fmaxf(accS[nt][0], accS[nt][1]));
            mx1 = fmaxf(mx1, fmaxf(accS[nt][2], accS[nt][3]));
        }
        mx0 = qmax(mx0); mx1 = qmax(mx1);
        float m0n = fmaxf(m0, mx0), m1n = fmaxf(m1, mx1);
        float c0 = ex2f(m0 - m0n), c1 = ex2f(m1 - m1n);
        m0 = m0n; m1 = m1n;
        float s0 = 0.0f, s1 = 0.0f;
        #pragma unroll
        for (int nt = 0; nt < 8; nt++) {
            accS[nt][0] = ex2f(accS[nt][0] - m0);
            accS[nt][1] = ex2f(accS[nt][1] - m0);
            accS[nt][2] = ex2f(accS[nt][2] - m1);
            accS[nt][3] = ex2f(accS[nt][3] - m1);
            s0 += accS[nt][0] + accS[nt][1];
            s1 += accS[nt][2] + accS[nt][3];
            accO[nt][0] *= c0; accO[nt][1] *= c0;
            accO[nt][2] *= c1; accO[nt][3] *= c1;
        }
        l0 = l0 * c0 + qsum(s0);
        l1 = l1 * c1 + qsum(s1);

        // ---- PV: Ph*Vh + Ph*Vl + Pl*Vh
        // A-frag order (PTX): a0=(r,klo) a1=(r+8,klo) a2=(r,khi) a3=(r+8,khi).
        // Natural packing from accS[2s] (kv-lo) and accS[2s+1] (kv-hi) gives
        // exactly this order — no rearrangement needed.
        const uint32_t vhb = kb + 24576, vlb = kb + 32768;
        #pragma unroll
        for (int s = 0; s < 4; s++) {
            uint32_t aPh[4], aPl[4];
            #pragma unroll
            for (int half = 0; half < 2; half++) {
                const float* a = accS[2 * s + half];
                uint32_t ph0 = packbf(a[1], a[0]);          // (r, k even|odd)
                uint32_t ph1 = packbf(a[3], a[2]);          // (r+8, k even|odd)
                float pl0e = a[0] - __uint_as_float(ph0 << 16);
                float pl0o = a[1] - __uint_as_float(ph0 & 0xffff0000u);
                float pl1e = a[2] - __uint_as_float(ph1 << 16);
                float pl1o = a[3] - __uint_as_float(ph1 & 0xffff0000u);
                aPh[2 * half]     = ph0;
                aPh[2 * half + 1] = ph1;
                aPl[2 * half]     = packbf(pl0o, pl0e);
                aPl[2 * half + 1] = packbf(pl1o, pl1e);
            }

            int vrow = s * 16 + ((lane >> 3) & 1) * 8 + (lane & 7);
            #pragma unroll
            for (int j = 0; j < 4; j++) {
                int colb = (j * 16 + ((lane >> 4) & 1) * 8) * 2;
                uint32_t vh[4], vl[4];
                ldsm4t(vh[0], vh[1], vh[2], vh[3],
                       vhb + sw128((uint32_t)(vrow * 128 + colb)));
                ldsm4t(vl[0], vl[1], vl[2], vl[3],
                       vlb + sw128((uint32_t)(vrow * 128 + colb)));
                mma16816(accO[2 * j],     aPh, &vh[0]);
                mma16816(accO[2 * j + 1], aPh, &vh[2]);
                mma16816(accO[2 * j],     aPh, &vl[0]);
                mma16816(accO[2 * j + 1], aPh, &vl[2]);
                mma16816(accO[2 * j],     aPl, &vh[0]);
                mma16816(accO[2 * j + 1], aPl, &vh[2]);
            }
        }

        __syncthreads();
        if (kt + 2 < NKV) fillKV(kt & 1, kt + 2);
        cp_commit();
        cp_wait1();
        __syncthreads();
    }

    // ---- epilogue: normalize + exclusive output mod, write g_Z
    const float inv0 = 1.0f / l0, inv1 = 1.0f / l1;
    const size_t grow0 = (size_t)(b_ * SEQ + q0 + wid * 16 + (lane >> 2));
    const int cbase = h_ * 64 + (lane & 3) * 2;

    #pragma unroll
    for (int rs = 0; rs < 2; rs++) {
        size_t grow = grow0 + rs * 8;
        float inv = rs ? inv1 : inv0;
        float vv[8][2];
        float vsq = 0.0f, ydv = 0.0f, ysq = 0.0f;
        #pragma unroll
        for (int nt = 0; nt < 8; nt++) {
            float2 vld = *(const float2*)(g_V + grow * 1024 + cbase + nt * 8);
            vv[nt][0] = vld.x; vv[nt][1] = vld.y;
            float y0 = accO[nt][2 * rs] * inv;
            float y1 = accO[nt][2 * rs + 1] * inv;
            accO[nt][2 * rs] = y0; accO[nt][2 * rs + 1] = y1;
            vsq = fmaf(vld.x, vld.x, fmaf(vld.y, vld.y, vsq));
            ydv = fmaf(y0, vld.x, fmaf(y1, vld.y, ydv));
            ysq = fmaf(y0, y0, fmaf(y1, y1, ysq));
        }
        vsq = qsum(vsq); ydv = qsum(ydv); ysq = qsum(ysq);
        float scale = (vsq > 0.0f) ? (ydv / fmaxf(vsq, FLT_MIN)) : 0.0f;
        float zsq = 0.0f;
        float zz[8][2];
        #pragma unroll
        for (int nt = 0; nt < 8; nt++) {
            float z0 = accO[nt][2 * rs] - scale * vv[nt][0];
            float z1 = accO[nt][2 * rs + 1] - scale * vv[nt][1];
            zz[nt][0] = z0; zz[nt][1] = z1;
            zsq = fmaf(z0, z0, fmaf(z1, z1, zsq));
        }
        zsq = qsum(zsq);
        float ref_norm = fmaxf(sqrtf(ysq), sqrtf(vsq));
        float tol = FLT_EPSILON * 64.0f * ref_norm;
        bool zero_out = (vsq > 0.0f) && (sqrtf(zsq) <= tol);
        #pragma unroll
        for (int nt = 0; nt < 8; nt++) {
            float2 o = zero_out ? make_float2(0.0f, 0.0f)
                                : make_float2(zz[nt][0], zz[nt][1]);
            *(float2*)(g_Z + grow * 1024 + cbase + nt * 8) = o;
        }
    }
}

// ---------------------------------------------------------------------------
extern "C" void kernel_launch(void* const* d_in, const int* in_sizes, int n_in,
                              void* d_out, int out_size)
{
    const float* x  = (const float*)d_in[0];
    const float* Wq = (const float*)d_in[1];
    const float* Wk = (const float*)d_in[2];
    const float* Wv = (const float*)d_in[3];
    const float* Wo = (const float*)d_in[4];
    float* out = (float*)d_out;

    cudaFuncSetAttribute(gemm3s_kernel, cudaFuncAttributeMaxDynamicSharedMemorySize, GSMEM);
    cudaFuncSetAttribute(attn_mma_kernel, cudaFuncAttributeMaxDynamicSharedMemorySize, ASMEM);

    convA_kernel<<<(ROWS * D_MODEL + 255) / 256, 256>>>(x, 0);
    convB_kernel<<<(D_MODEL * D_MODEL + 255) / 256, 256>>>(Wq, 0);
    convB_kernel<<<(D_MODEL * D_MODEL + 255) / 256, 256>>>(Wk, 1);
    convB_kernel<<<(D_MODEL * D_MODEL + 255) / 256, 256>>>(Wv, 2);
    convB_kernel<<<(D_MODEL * D_MODEL + 255) / 256, 256>>>(Wo, 3);

    dim3 gqkv(3 * D_MODEL / BNg, ROWS / BMg);
    gemm3s_kernel<<<gqkv, 512, GSMEM>>>(nullptr, 0);

    convAttn_kernel<<<(ROWS * D_MODEL + 255) / 256, 256>>>();

    dim3 gattn(NBH, SEQ / 256);
    attn_mma_kernel<<<gattn, 512, ASMEM>>>();

    convA_kernel<<<(ROWS * D_MODEL + 255) / 256, 256>>>(nullptr, 1);
    dim3 gout(D_MODEL / BNg, ROWS / BMg);
    gemm3s_kernel<<<gout, 512, GSMEM>>>(out, 1);
}

// round 6
// speedup vs baseline: 3.7351x; 1.2962x over previous
#include <cuda_runtime.h>
#include <cuda_bf16.h>
#include <math_constants.h>
#include <cfloat>
#include <cstdint>

#define D_MODEL 1024
#define NHEADS  16
#define DHEAD   64
#define BATCH   2
#define SEQ     2048
#define ROWS    (BATCH * SEQ)   // 4096
#define NBH     (BATCH * NHEADS)
#define QSCALE  0.18033688011112042f   // 0.125 * log2(e)

// 2-slot operands. Layout for GEMM A/B: [row][chunk32][hi 32 | lo 32], row stride 2048 elems.
__device__ __nv_bfloat16 g_Xs2[ROWS * 2048];
__device__ __nv_bfloat16 g_Zs2[ROWS * 2048];
__device__ __nv_bfloat16 g_Wqkv2[3 * D_MODEL * 2048];
__device__ __nv_bfloat16 g_Wo2[D_MODEL * 2048];
// attention per-head panels: [bh][t][64]
__device__ __nv_bfloat16 g_Qh[NBH * SEQ * DHEAD];
__device__ __nv_bfloat16 g_Ql[NBH * SEQ * DHEAD];
__device__ __nv_bfloat16 g_Kh[NBH * SEQ * DHEAD];
__device__ __nv_bfloat16 g_Kl[NBH * SEQ * DHEAD];
__device__ __nv_bfloat16 g_Vh[NBH * SEQ * DHEAD];
__device__ __nv_bfloat16 g_Vl[NBH * SEQ * DHEAD];

// ---------------------------------------------------------------------------
// helpers
// ---------------------------------------------------------------------------
__device__ __forceinline__ uint32_t smem_u32(const void* p) {
    uint32_t a;
    asm("{ .reg .u64 t; cvta.to.shared.u64 t, %1; cvt.u32.u64 %0, t; }" : "=r"(a) : "l"(p));
    return a;
}
__device__ __forceinline__ void cp_async16(uint32_t dst, const void* src) {
    asm volatile("cp.async.cg.shared.global [%0], [%1], 16;" :: "r"(dst), "l"(src) : "memory");
}
__device__ __forceinline__ void cp_commit() {
    asm volatile("cp.async.commit_group;" ::: "memory");
}
__device__ __forceinline__ void cp_wait2() {
    asm volatile("cp.async.wait_group 2;" ::: "memory");
}
__device__ __forceinline__ uint32_t sw128(uint32_t off) { return off ^ ((off >> 3) & 0x70); }
__device__ __forceinline__ void ldsm4(uint32_t& r0, uint32_t& r1, uint32_t& r2, uint32_t& r3,
                                      uint32_t addr) {
    asm volatile("ldmatrix.sync.aligned.m8n8.x4.shared.b16 {%0,%1,%2,%3}, [%4];"
                 : "=r"(r0), "=r"(r1), "=r"(r2), "=r"(r3) : "r"(addr));
}
__device__ __forceinline__ void ldsm4t(uint32_t& r0, uint32_t& r1, uint32_t& r2, uint32_t& r3,
                                       uint32_t addr) {
    asm volatile("ldmatrix.sync.aligned.m8n8.x4.trans.shared.b16 {%0,%1,%2,%3}, [%4];"
                 : "=r"(r0), "=r"(r1), "=r"(r2), "=r"(r3) : "r"(addr));
}
__device__ __forceinline__ void mma16816(float* c, const uint32_t* a, const uint32_t* b) {
    asm volatile(
        "mma.sync.aligned.m16n8k16.row.col.f32.bf16.bf16.f32 "
        "{%0,%1,%2,%3}, {%4,%5,%6,%7}, {%8,%9}, {%0,%1,%2,%3};"
        : "+f"(c[0]), "+f"(c[1]), "+f"(c[2]), "+f"(c[3])
        : "r"(a[0]), "r"(a[1]), "r"(a[2]), "r"(a[3]), "r"(b[0]), "r"(b[1]));
}
__device__ __forceinline__ float ex2f(float x) {
    float y; asm("ex2.approx.ftz.f32 %0, %1;" : "=f"(y) : "f"(x)); return y;
}
__device__ __forceinline__ uint32_t packbf(float hi, float lo) {
    uint32_t r; asm("cvt.rn.bf16x2.f32 %0, %1, %2;" : "=r"(r) : "f"(hi), "f"(lo)); return r;
}
__device__ __forceinline__ float qsum(float v) {
    v += __shfl_xor_sync(0xffffffffu, v, 1);
    v += __shfl_xor_sync(0xffffffffu, v, 2);
    return v;
}
__device__ __forceinline__ float qmax(float v) {
    v = fmaxf(v, __shfl_xor_sync(0xffffffffu, v, 1));
    v = fmaxf(v, __shfl_xor_sync(0xffffffffu, v, 2));
    return v;
}
__device__ __forceinline__ void split2(float x, __nv_bfloat16& h, __nv_bfloat16& l) {
    h = __float2bfloat16_rn(x);
    l = __float2bfloat16_rn(x - __bfloat162float(h));
}

// ---------------------------------------------------------------------------
// conversions (input x and the 4 weights only; everything else is fused)
// 2-slot layout: idx = row*2048 + (c>>5)*64 + (c&31), lo at +32.
// ---------------------------------------------------------------------------
__global__ void convX_kernel(const float* __restrict__ src)
{
    int i = blockIdx.x * blockDim.x + threadIdx.x;
    if (i >= ROWS * D_MODEL) return;
    int row = i >> 10, c = i & 1023;
    __nv_bfloat16 h, l;
    split2(src[i], h, l);
    size_t o = (size_t)row * 2048 + (c >> 5) * 64 + (c & 31);
    g_Xs2[o] = h; g_Xs2[o + 32] = l;
}

__global__ void convW_kernel(const float* __restrict__ Wq, const float* __restrict__ Wk,
                             const float* __restrict__ Wv, const float* __restrict__ Wo)
{
    int which = blockIdx.y;
    const float* src = (which == 0) ? Wq : (which == 1) ? Wk : (which == 2) ? Wv : Wo;
    __nv_bfloat16* dst = (which < 3) ? (g_Wqkv2 + (size_t)which * D_MODEL * 2048) : g_Wo2;
    int i = blockIdx.x * blockDim.x + threadIdx.x;
    if (i >= D_MODEL * D_MODEL) return;
    int row = i >> 10, c = i & 1023;
    __nv_bfloat16 h, l;
    split2(src[i], h, l);
    size_t o = (size_t)row * 2048 + (c >> 5) * 64 + (c & 31);
    dst[o] = h; dst[o + 32] = l;
}

// ---------------------------------------------------------------------------
// 2-slot HMMA GEMM: C = A * B^T over logical K=1024.
// CTA 256x128, chunk = 32 original k (128B/row: hi 64B | lo 64B), 3 stages.
// mode 0: A=g_Xs2, B=g_Wqkv2 (N=3072) -> epilogue splits into Qh/Ql/Kh/Kl/Vh/Vl.
// mode 1: A=g_Zs2, B=g_Wo2 (N=1024) -> epilogue writes fp32 outp.
// ---------------------------------------------------------------------------
#define BMg 256
#define BNg 128
#define NCH 32
#define STA (BMg * 128)        // 32768
#define STB (BNg * 128)        // 16384
#define STAGE (STA + STB)      // 49152
#define GSMEM (3 * STAGE)      // 147456

__global__ void __launch_bounds__(512, 1)
gemm2s_kernel(float* __restrict__ outp, int mode)
{
    extern __shared__ char smem[];
    const uint32_t sbase = smem_u32(smem);
    const int tid = threadIdx.x;
    const int wid = tid >> 5;
    const int lane = tid & 31;
    const int wm = wid >> 2;
    const int wn = wid & 3;
    const int m0 = blockIdx.y * BMg;
    const int n0 = blockIdx.x * BNg;

    const __nv_bfloat16* A = (mode == 0) ? g_Xs2 : g_Zs2;
    const __nv_bfloat16* B = (mode == 0) ? g_Wqkv2 : g_Wo2;
    const __nv_bfloat16* Abase = A + (size_t)m0 * 2048;
    const __nv_bfloat16* Bbase = B + (size_t)n0 * 2048;

    auto fill = [&](int stage, int chunk) {
        uint32_t base = sbase + stage * STAGE;
        #pragma unroll
        for (int i = 0; i < 6; i++) {
            int g = i * 512 + tid;
            if (g < 2048) {                 // A: 256 rows x 8 granules
                int row = g >> 3, gr = g & 7;
                cp_async16(base + sw128((uint32_t)(row * 128 + gr * 16)),
                           Abase + (size_t)row * 2048 + chunk * 64 + gr * 8);
            } else {                        // B: 128 rows x 8 granules
                int bi = g - 2048;
                int row = bi >> 3, gr = bi & 7;
                cp_async16(base + STA + sw128((uint32_t)(row * 128 + gr * 16)),
                           Bbase + (size_t)row * 2048 + chunk * 64 + gr * 8);
            }
        }
    };

    float acc[4][4][4] = {};

    fill(0, 0); cp_commit();
    fill(1, 1); cp_commit();

    for (int c = 0; c < NCH; c++) {
        if (c + 2 < NCH) fill((c + 2) % 3, c + 2);
        cp_commit();
        cp_wait2();
        __syncthreads();

        uint32_t abase = sbase + (c % 3) * STAGE;
        uint32_t bbase = abase + STA;

        #pragma unroll
        for (int s = 0; s < 2; s++) {
            const int kb = s * 32;         // byte offset within hi half
            uint32_t af[4][4];
            // ah
            #pragma unroll
            for (int mt = 0; mt < 4; mt++) {
                int row = wm * 64 + mt * 16 + (lane & 15);
                ldsm4(af[mt][0], af[mt][1], af[mt][2], af[mt][3],
                      abase + sw128((uint32_t)(row * 128 + kb + (lane >> 4) * 16)));
            }
            // bh
            uint32_t bh[4][2];
            #pragma unroll
            for (int bt = 0; bt < 2; bt++) {
                int row = wn * 32 + bt * 16 + (lane & 7) + ((lane >> 4) & 1) * 8;
                int col = kb + (((lane >> 3) & 1) * 16);
                ldsm4(bh[2 * bt][0], bh[2 * bt][1], bh[2 * bt + 1][0], bh[2 * bt + 1][1],
                      bbase + sw128((uint32_t)(row * 128 + col)));
            }
            #pragma unroll
            for (int mt = 0; mt < 4; mt++)
                #pragma unroll
                for (int nt = 0; nt < 4; nt++)
                    mma16816(acc[mt][nt], af[mt], bh[nt]);
            // bl (reuse ah)
            uint32_t bl[4][2];
            #pragma unroll
            for (int bt = 0; bt < 2; bt++) {
                int row = wn * 32 + bt * 16 + (lane & 7) + ((lane >> 4) & 1) * 8;
                int col = 64 + kb + (((lane >> 3) & 1) * 16);
                ldsm4(bl[2 * bt][0], bl[2 * bt][1], bl[2 * bt + 1][0], bl[2 * bt + 1][1],
                      bbase + sw128((uint32_t)(row * 128 + col)));
            }
            #pragma unroll
            for (int mt = 0; mt < 4; mt++)
                #pragma unroll
                for (int nt = 0; nt < 4; nt++)
                    mma16816(acc[mt][nt], af[mt], bl[nt]);
            // al (reuse bh)
            #pragma unroll
            for (int mt = 0; mt < 4; mt++) {
                int row = wm * 64 + mt * 16 + (lane & 15);
                ldsm4(af[mt][0], af[mt][1], af[mt][2], af[mt][3],
                      abase + sw128((uint32_t)(row * 128 + 64 + kb + (lane >> 4) * 16)));
            }
            #pragma unroll
            for (int mt = 0; mt < 4; mt++)
                #pragma unroll
                for (int nt = 0; nt < 4; nt++)
                    mma16816(acc[mt][nt], af[mt], bh[nt]);
        }
        __syncthreads();
    }

    // ---- epilogue
    const int gid = lane >> 2;
    const int tid2 = lane & 3;
    if (mode == 1) {
        #pragma unroll
        for (int mt = 0; mt < 4; mt++) {
            int row0 = m0 + wm * 64 + mt * 16 + gid;
            #pragma unroll
            for (int nt = 0; nt < 4; nt++) {
                int ncol = n0 + wn * 32 + nt * 8 + tid2 * 2;
                *(float2*)(outp + (size_t)row0 * 1024 + ncol) =
                    make_float2(acc[mt][nt][0], acc[mt][nt][1]);
                *(float2*)(outp + (size_t)(row0 + 8) * 1024 + ncol) =
                    make_float2(acc[mt][nt][2], acc[mt][nt][3]);
            }
        }
        return;
    }
    // mode 0: split into per-head hi/lo panels
    #pragma unroll
    for (int mt = 0; mt < 4; mt++) {
        int row0 = m0 + wm * 64 + mt * 16 + gid;
        #pragma unroll
        for (int nt = 0; nt < 4; nt++) {
            int ncol = n0 + wn * 32 + nt * 8 + tid2 * 2;
            int which = ncol >> 10;          // 0=Q 1=K 2=V
            int c = ncol & 1023;
            int h = c >> 6, d = c & 63;
            __nv_bfloat16* hiA = (which == 0) ? g_Qh : (which == 1) ? g_Kh : g_Vh;
            __nv_bfloat16* loA = (which == 0) ? g_Ql : (which == 1) ? g_Kl : g_Vl;
            float sc = (which == 0) ? QSCALE : 1.0f;
            #pragma unroll
            for (int rr = 0; rr < 2; rr++) {
                int row = row0 + rr * 8;
                int b = row >> 11, t = row & 2047;
                size_t base = ((size_t)(b * NHEADS + h) * SEQ + t) * 64 + d;
                float v0 = acc[mt][nt][2 * rr] * sc;
                float v1 = acc[mt][nt][2 * rr + 1] * sc;
                __nv_bfloat16 h0, l0, h1, l1;
                split2(v0, h0, l0); split2(v1, h1, l1);
                *(__nv_bfloat162*)(hiA + base) = __nv_bfloat162(h0, h1);
                *(__nv_bfloat162*)(loA + base) = __nv_bfloat162(l0, l1);
            }
        }
    }
}

// ---------------------------------------------------------------------------
// 2-slot HMMA flash attention + exclusive output mod
// CTA: 256 q rows, 16 warps. KV tile 64, 3-stage pipeline.
// Smem: Qh 32KB + Ql 32KB + 3 stages x (Kh|Kl|Vh|Vl 8KB each = 32KB) = 160KB.
// ---------------------------------------------------------------------------
#define AQ (2 * 32768)
#define AST 32768
#define ASMEM (AQ + 3 * AST)     // 163840
#define NKV (SEQ / 64)           // 32

__global__ void __launch_bounds__(512, 1)
attn_mma_kernel()
{
    extern __shared__ char smem[];
    const uint32_t sb = smem_u32(smem);
    const int tid = threadIdx.x;
    const int wid = tid >> 5;
    const int lane = tid & 31;
    const int bh = blockIdx.x;
    const int q0 = blockIdx.y * 256;
    const int b_ = bh >> 4, h_ = bh & 15;

    const __nv_bfloat16* Qhs = g_Qh + ((size_t)bh * SEQ + q0) * 64;
    const __nv_bfloat16* Qls = g_Ql + ((size_t)bh * SEQ + q0) * 64;
    const __nv_bfloat16* Khs = g_Kh + (size_t)bh * SEQ * 64;
    const __nv_bfloat16* Kls = g_Kl + (size_t)bh * SEQ * 64;
    const __nv_bfloat16* Vhs = g_Vh + (size_t)bh * SEQ * 64;
    const __nv_bfloat16* Vls = g_Vl + (size_t)bh * SEQ * 64;

    // Q fill: 2 panels x 256 rows x 8 granules = 4096
    #pragma unroll
    for (int i = 0; i < 8; i++) {
        int g = i * 512 + tid;
        int panel = g >> 11, idx = g & 2047;
        int row = idx >> 3, gr = idx & 7;
        const __nv_bfloat16* src = (panel ? Qls : Qhs) + (size_t)row * 64 + gr * 8;
        cp_async16(sb + panel * 32768 + sw128((uint32_t)(row * 128 + gr * 16)), src);
    }
    auto fillKV = [&](int stage, int kt) {
        uint32_t base = sb + AQ + stage * AST;
        int t0 = kt * 64;
        #pragma unroll
        for (int i = 0; i < 4; i++) {
            int g = i * 512 + tid;
            int seg = g >> 9, idx = g & 511;
            int row = idx >> 3, gr = idx & 7;
            const __nv_bfloat16* src =
                (seg == 0) ? Khs : (seg == 1) ? Kls : (seg == 2) ? Vhs : Vls;
            cp_async16(base + seg * 8192 + sw128((uint32_t)(row * 128 + gr * 16)),
                       src + (size_t)(t0 + row) * 64 + gr * 8);
        }
    };

    cp_commit();                 // G0: Q
    fillKV(0, 0); cp_commit();
    fillKV(1, 1); cp_commit();
    fillKV(2, 2); cp_commit();

    float accO[8][4] = {};
    float m0 = -CUDART_INF_F, m1 = -CUDART_INF_F;
    float l0 = 0.0f, l1 = 0.0f;

    cp_wait2();                  // Q + kv0 complete
    __syncthreads();

    for (int kt = 0; kt < NKV; kt++) {
        const uint32_t kb = sb + AQ + (kt % 3) * AST;
        const uint32_t klb = kb + 8192;

        // ---- S = Qh*Kh + Qh*Kl + Ql*Kh
        float accS[8][4] = {};
        const int arow = wid * 16 + (lane & 15);
        #pragma unroll
        for (int s = 0; s < 4; s++) {
            const int cb = s * 32 + (lane >> 4) * 16;
            uint32_t ah[4], al[4];
            ldsm4(ah[0], ah[1], ah[2], ah[3], sb + sw128((uint32_t)(arow * 128 + cb)));
            ldsm4(al[0], al[1], al[2], al[3], sb + 32768 + sw128((uint32_t)(arow * 128 + cb)));
            #pragma unroll
            for (int nb = 0; nb < 4; nb++) {
                int row = nb * 16 + (lane & 7) + ((lane >> 4) & 1) * 8;
                int off = s * 32 + ((lane >> 3) & 1) * 16;
                uint32_t bhf[4], blf[4];
                ldsm4(bhf[0], bhf[1], bhf[2], bhf[3],
                      kb + sw128((uint32_t)(row * 128 + off)));
                ldsm4(blf[0], blf[1], blf[2], blf[3],
                      klb + sw128((uint32_t)(row * 128 + off)));
                mma16816(accS[2 * nb],     ah, &bhf[0]);
                mma16816(accS[2 * nb + 1], ah, &bhf[2]);
                mma16816(accS[2 * nb],     ah, &blf[0]);
                mma16816(accS[2 * nb + 1], ah, &blf[2]);
                mma16816(accS[2 * nb],     al, &bhf[0]);
                mma16816(accS[2 * nb + 1], al, &bhf[2]);
            }
        }

        // ---- online softmax (base-2)
        float mx0 = -CUDART_INF_F, mx1 = -CUDART_INF_F;
        #pragma unroll
        for (int nt = 0; nt < 8; nt++) {
            mx0 = fmaxf(mx0, fmaxf(accS[nt][0], accS[nt][1]));
            mx1 = fmaxf(mx1, fmaxf(accS[nt][2], accS[nt][3]));
        }
        mx0 = qmax(mx0); mx1 = qmax(mx1);
        float m0n = fmaxf(m0, mx0), m1n = fmaxf(m1, mx1);
        float c0 = ex2f(m0 - m0n), c1 = ex2f(m1 - m1n);
        m0 = m0n; m1 = m1n;
        float s0 = 0.0f, s1 = 0.0f;
        #pragma unroll
        for (int nt = 0; nt < 8; nt++) {
            accS[nt][0] = ex2f(accS[nt][0] - m0);
            accS[nt][1] = ex2f(accS[nt][1] - m0);
            accS[nt][2] = ex2f(accS[nt][2] - m1);
            accS[nt][3] = ex2f(accS[nt][3] - m1);
            s0 += accS[nt][0] + accS[nt][1];
            s1 += accS[nt][2] + accS[nt][3];
            accO[nt][0] *= c0; accO[nt][1] *= c0;
            accO[nt][2] *= c1; accO[nt][3] *= c1;
        }
        l0 = l0 * c0 + qsum(s0);
        l1 = l1 * c1 + qsum(s1);

        // ---- PV: Ph*Vh + Ph*Vl + Pl*Vh (natural A-frag packing, validated R5)
        const uint32_t vhb = kb + 16384, vlb = kb + 24576;
        #pragma unroll
        for (int s = 0; s < 4; s++) {
            uint32_t aPh[4], aPl[4];
            #pragma unroll
            for (int half = 0; half < 2; half++) {
                const float* a = accS[2 * s + half];
                uint32_t ph0 = packbf(a[1], a[0]);
                uint32_t ph1 = packbf(a[3], a[2]);
                float pl0e = a[0] - __uint_as_float(ph0 << 16);
                float pl0o = a[1] - __uint_as_float(ph0 & 0xffff0000u);
                float pl1e = a[2] - __uint_as_float(ph1 << 16);
                float pl1o = a[3] - __uint_as_float(ph1 & 0xffff0000u);
                aPh[2 * half]     = ph0;
                aPh[2 * half + 1] = ph1;
                aPl[2 * half]     = packbf(pl0o, pl0e);
                aPl[2 * half + 1] = packbf(pl1o, pl1e);
            }
            int vrow = s * 16 + ((lane >> 3) & 1) * 8 + (lane & 7);
            #pragma unroll
            for (int j = 0; j < 4; j++) {
                int colb = (j * 16 + ((lane >> 4) & 1) * 8) * 2;
                uint32_t vh[4], vl[4];
                ldsm4t(vh[0], vh[1], vh[2], vh[3],
                       vhb + sw128((uint32_t)(vrow * 128 + colb)));
                ldsm4t(vl[0], vl[1], vl[2], vl[3],
                       vlb + sw128((uint32_t)(vrow * 128 + colb)));
                mma16816(accO[2 * j],     aPh, &vh[0]);
                mma16816(accO[2 * j + 1], aPh, &vh[2]);
                mma16816(accO[2 * j],     aPh, &vl[0]);
                mma16816(accO[2 * j + 1], aPh, &vl[2]);
                mma16816(accO[2 * j],     aPl, &vh[0]);
                mma16816(accO[2 * j + 1], aPl, &vh[2]);
            }
        }

        __syncthreads();
        if (kt + 3 < NKV) fillKV(kt % 3, kt + 3);
        cp_commit();
        cp_wait2();              // fill for kt+1 complete
        __syncthreads();
    }

    // ---- epilogue: normalize + exclusive output mod, write Z directly in 2-slot
    const float inv0 = 1.0f / l0, inv1 = 1.0f / l1;
    const int t_base = q0 + wid * 16 + (lane >> 2);
    const int dbase = (lane & 3) * 2;

    #pragma unroll
    for (int rs = 0; rs < 2; rs++) {
        int t = t_base + rs * 8;
        float inv = rs ? inv1 : inv0;
        float vv[8][2];
        float vsq = 0.0f, ydv = 0.0f, ysq = 0.0f;
        #pragma unroll
        for (int nt = 0; nt < 8; nt++) {
            size_t vb = ((size_t)bh * SEQ + t) * 64 + dbase + nt * 8;
            __nv_bfloat162 vh2 = *(const __nv_bfloat162*)(g_Vh + vb);
            __nv_bfloat162 vl2 = *(const __nv_bfloat162*)(g_Vl + vb);
            float vx = __bfloat162float(vh2.x) + __bfloat162float(vl2.x);
            float vy = __bfloat162float(vh2.y) + __bfloat162float(vl2.y);
            vv[nt][0] = vx; vv[nt][1] = vy;
            float y0 = accO[nt][2 * rs] * inv;
            float y1 = accO[nt][2 * rs + 1] * inv;
            accO[nt][2 * rs] = y0; accO[nt][2 * rs + 1] = y1;
            vsq = fmaf(vx, vx, fmaf(vy, vy, vsq));
            ydv = fmaf(y0, vx, fmaf(y1, vy, ydv));
            ysq = fmaf(y0, y0, fmaf(y1, y1, ysq));
        }
        vsq = qsum(vsq); ydv = qsum(ydv); ysq = qsum(ysq);
        float scale = (vsq > 0.0f) ? (ydv / fmaxf(vsq, FLT_MIN)) : 0.0f;
        float zsq = 0.0f;
        float zz[8][2];
        #pragma unroll
        for (int nt = 0; nt < 8; nt++) {
            float z0 = accO[nt][2 * rs] - scale * vv[nt][0];
            float z1 = accO[nt][2 * rs + 1] - scale * vv[nt][1];
            zz[nt][0] = z0; zz[nt][1] = z1;
            zsq = fmaf(z0, z0, fmaf(z1, z1, zsq));
        }
        zsq = qsum(zsq);
        float ref_norm = fmaxf(sqrtf(ysq), sqrtf(vsq));
        float tol = FLT_EPSILON * 64.0f * ref_norm;
        bool zero_out = (vsq > 0.0f) && (sqrtf(zsq) <= tol);
        size_t zrow = (size_t)(b_ * SEQ + t) * 2048;
        #pragma unroll
        for (int nt = 0; nt < 8; nt++) {
            float z0 = zero_out ? 0.0f : zz[nt][0];
            float z1 = zero_out ? 0.0f : zz[nt][1];
            int c = h_ * 64 + dbase + nt * 8;
            size_t o = zrow + (c >> 5) * 64 + (c & 31);
            __nv_bfloat16 h0, l0b, h1, l1b;
            split2(z0, h0, l0b); split2(z1, h1, l1b);
            *(__nv_bfloat162*)(g_Zs2 + o) = __nv_bfloat162(h0, h1);
            *(__nv_bfloat162*)(g_Zs2 + o + 32) = __nv_bfloat162(l0b, l1b);
        }
    }
}

// ---------------------------------------------------------------------------
extern "C" void kernel_launch(void* const* d_in, const int* in_sizes, int n_in,
                              void* d_out, int out_size)
{
    const float* x  = (const float*)d_in[0];
    const float* Wq = (const float*)d_in[1];
    const float* Wk = (const float*)d_in[2];
    const float* Wv = (const float*)d_in[3];
    const float* Wo = (const float*)d_in[4];
    float* out = (float*)d_out;

    cudaFuncSetAttribute(gemm2s_kernel, cudaFuncAttributeMaxDynamicSharedMemorySize, GSMEM);
    cudaFuncSetAttribute(attn_mma_kernel, cudaFuncAttributeMaxDynamicSharedMemorySize, ASMEM);

    convX_kernel<<<(ROWS * D_MODEL + 255) / 256, 256>>>(x);
    dim3 gw((D_MODEL * D_MODEL + 255) / 256, 4);
    convW_kernel<<<gw, 256>>>(Wq, Wk, Wv, Wo);

    // fused QKV projection -> per-head hi/lo panels
    dim3 gqkv(3 * D_MODEL / BNg, ROWS / BMg);   // (24, 16)
    gemm2s_kernel<<<gqkv, 512, GSMEM>>>(nullptr, 0);

    // attention (writes g_Zs2 directly)
    dim3 gattn(NBH, SEQ / 256);
    attn_mma_kernel<<<gattn, 512, ASMEM>>>();

    // output projection
    dim3 gout(D_MODEL / BNg, ROWS / BMg);       // (8, 16)
    gemm2s_kernel<<<gout, 512, GSMEM>>>(out, 1);
}

// round 7
// speedup vs baseline: 3.8477x; 1.0301x over previous
#include <cuda_runtime.h>
#include <cuda_bf16.h>
#include <math_constants.h>
#include <cfloat>
#include <cstdint>

#define D_MODEL 1024
#define NHEADS  16
#define DHEAD   64
#define BATCH   2
#define SEQ     2048
#define ROWS    (BATCH * SEQ)   // 4096
#define NBH     (BATCH * NHEADS)
#define QSCALE  0.18033688011112042f   // 0.125 * log2(e)

// 2-slot operands. GEMM A/B layout: [row][chunk32][hi 32 | lo 32], row stride 2048.
__device__ __nv_bfloat16 g_Xs2[ROWS * 2048];
__device__ __nv_bfloat16 g_Zs2[ROWS * 2048];
__device__ __nv_bfloat16 g_Wqkv2[3 * D_MODEL * 2048];
__device__ __nv_bfloat16 g_Wo2[D_MODEL * 2048];
// attention per-head panels: [bh][t][64]
__device__ __nv_bfloat16 g_Qh[NBH * SEQ * DHEAD];
__device__ __nv_bfloat16 g_Ql[NBH * SEQ * DHEAD];
__device__ __nv_bfloat16 g_Kh[NBH * SEQ * DHEAD];
__device__ __nv_bfloat16 g_Kl[NBH * SEQ * DHEAD];
__device__ __nv_bfloat16 g_Vh[NBH * SEQ * DHEAD];
__device__ __nv_bfloat16 g_Vl[NBH * SEQ * DHEAD];

// ---------------------------------------------------------------------------
// helpers
// ---------------------------------------------------------------------------
__device__ __forceinline__ uint32_t smem_u32(const void* p) {
    uint32_t a;
    asm("{ .reg .u64 t; cvta.to.shared.u64 t, %1; cvt.u32.u64 %0, t; }" : "=r"(a) : "l"(p));
    return a;
}
__device__ __forceinline__ void cp_async16(uint32_t dst, const void* src) {
    asm volatile("cp.async.cg.shared.global [%0], [%1], 16;" :: "r"(dst), "l"(src) : "memory");
}
__device__ __forceinline__ void cp_commit() {
    asm volatile("cp.async.commit_group;" ::: "memory");
}
__device__ __forceinline__ void cp_wait1() {
    asm volatile("cp.async.wait_group 1;" ::: "memory");
}
__device__ __forceinline__ void cp_wait2() {
    asm volatile("cp.async.wait_group 2;" ::: "memory");
}
__device__ __forceinline__ uint32_t sw128(uint32_t off) { return off ^ ((off >> 3) & 0x70); }
__device__ __forceinline__ void ldsm4(uint32_t& r0, uint32_t& r1, uint32_t& r2, uint32_t& r3,
                                      uint32_t addr) {
    asm volatile("ldmatrix.sync.aligned.m8n8.x4.shared.b16 {%0,%1,%2,%3}, [%4];"
                 : "=r"(r0), "=r"(r1), "=r"(r2), "=r"(r3) : "r"(addr));
}
__device__ __forceinline__ void ldsm4t(uint32_t& r0, uint32_t& r1, uint32_t& r2, uint32_t& r3,
                                       uint32_t addr) {
    asm volatile("ldmatrix.sync.aligned.m8n8.x4.trans.shared.b16 {%0,%1,%2,%3}, [%4];"
                 : "=r"(r0), "=r"(r1), "=r"(r2), "=r"(r3) : "r"(addr));
}
__device__ __forceinline__ void mma16816(float* c, const uint32_t* a, const uint32_t* b) {
    asm volatile(
        "mma.sync.aligned.m16n8k16.row.col.f32.bf16.bf16.f32 "
        "{%0,%1,%2,%3}, {%4,%5,%6,%7}, {%8,%9}, {%0,%1,%2,%3};"
        : "+f"(c[0]), "+f"(c[1]), "+f"(c[2]), "+f"(c[3])
        : "r"(a[0]), "r"(a[1]), "r"(a[2]), "r"(a[3]), "r"(b[0]), "r"(b[1]));
}
__device__ __forceinline__ float ex2f(float x) {
    float y; asm("ex2.approx.ftz.f32 %0, %1;" : "=f"(y) : "f"(x)); return y;
}
__device__ __forceinline__ uint32_t packbf(float hi, float lo) {
    uint32_t r; asm("cvt.rn.bf16x2.f32 %0, %1, %2;" : "=r"(r) : "f"(hi), "f"(lo)); return r;
}
__device__ __forceinline__ float qsum(float v) {
    v += __shfl_xor_sync(0xffffffffu, v, 1);
    v += __shfl_xor_sync(0xffffffffu, v, 2);
    return v;
}
__device__ __forceinline__ float qmax(float v) {
    v = fmaxf(v, __shfl_xor_sync(0xffffffffu, v, 1));
    v = fmaxf(v, __shfl_xor_sync(0xffffffffu, v, 2));
    return v;
}
__device__ __forceinline__ void split2(float x, __nv_bfloat16& h, __nv_bfloat16& l) {
    h = __float2bfloat16_rn(x);
    l = __float2bfloat16_rn(x - __bfloat162float(h));
}

// ---------------------------------------------------------------------------
// conversions
// ---------------------------------------------------------------------------
__global__ void convX_kernel(const float* __restrict__ src)
{
    int i = blockIdx.x * blockDim.x + threadIdx.x;
    if (i >= ROWS * D_MODEL) return;
    int row = i >> 10, c = i & 1023;
    __nv_bfloat16 h, l;
    split2(src[i], h, l);
    size_t o = (size_t)row * 2048 + (c >> 5) * 64 + (c & 31);
    g_Xs2[o] = h; g_Xs2[o + 32] = l;
}

__global__ void convW_kernel(const float* __restrict__ Wq, const float* __restrict__ Wk,
                             const float* __restrict__ Wv, const float* __restrict__ Wo)
{
    int which = blockIdx.y;
    const float* src = (which == 0) ? Wq : (which == 1) ? Wk : (which == 2) ? Wv : Wo;
    __nv_bfloat16* dst = (which < 3) ? (g_Wqkv2 + (size_t)which * D_MODEL * 2048) : g_Wo2;
    int i = blockIdx.x * blockDim.x + threadIdx.x;
    if (i >= D_MODEL * D_MODEL) return;
    int row = i >> 10, c = i & 1023;
    __nv_bfloat16 h, l;
    split2(src[i], h, l);
    size_t o = (size_t)row * 2048 + (c >> 5) * 64 + (c & 31);
    dst[o] = h; dst[o + 32] = l;
}

// ---------------------------------------------------------------------------
// 2-slot HMMA GEMM: C = A * B^T over logical K=1024.
// CTA 128x128, 256 threads (8 warps, 2x4 grid of 64x32 warp tiles), 3 stages.
// 2 CTAs/SM (RF: 256*128*2 = 64K; smem 96KB*2 = 192KB).
// ---------------------------------------------------------------------------
#define BMg 128
#define BNg 128
#define NCH 32
#define STA (BMg * 128)        // 16384
#define STB (BNg * 128)        // 16384
#define STAGE (STA + STB)      // 32768
#define GSMEM (3 * STAGE)      // 98304

__global__ void __launch_bounds__(256, 2)
gemm2s_kernel(float* __restrict__ outp, int mode)
{
    extern __shared__ char smem[];
    const uint32_t sbase = smem_u32(smem);
    const int tid = threadIdx.x;
    const int wid = tid >> 5;
    const int lane = tid & 31;
    const int wm = wid >> 2;        // 0..1
    const int wn = wid & 3;         // 0..3
    const int m0 = blockIdx.y * BMg;
    const int n0 = blockIdx.x * BNg;

    const __nv_bfloat16* A = (mode == 0) ? g_Xs2 : g_Zs2;
    const __nv_bfloat16* B = (mode == 0) ? g_Wqkv2 : g_Wo2;
    const __nv_bfloat16* Abase = A + (size_t)m0 * 2048;
    const __nv_bfloat16* Bbase = B + (size_t)n0 * 2048;

    auto fill = [&](int stage, int chunk) {
        uint32_t base = sbase + stage * STAGE;
        #pragma unroll
        for (int i = 0; i < 8; i++) {
            int g = i * 256 + tid;
            if (g < 1024) {                 // A: 128 rows x 8 granules
                int row = g >> 3, gr = g & 7;
                cp_async16(base + sw128((uint32_t)(row * 128 + gr * 16)),
                           Abase + (size_t)row * 2048 + chunk * 64 + gr * 8);
            } else {                        // B: 128 rows x 8 granules
                int bi = g - 1024;
                int row = bi >> 3, gr = bi & 7;
                cp_async16(base + STA + sw128((uint32_t)(row * 128 + gr * 16)),
                           Bbase + (size_t)row * 2048 + chunk * 64 + gr * 8);
            }
        }
    };

    float acc[4][4][4] = {};

    fill(0, 0); cp_commit();
    fill(1, 1); cp_commit();

    for (int c = 0; c < NCH; c++) {
        if (c + 2 < NCH) fill((c + 2) % 3, c + 2);
        cp_commit();
        cp_wait2();
        __syncthreads();

        uint32_t abase = sbase + (c % 3) * STAGE;
        uint32_t bbase = abase + STA;

        #pragma unroll
        for (int s = 0; s < 2; s++) {
            const int kb = s * 32;
            uint32_t af[4][4];
            // ah
            #pragma unroll
            for (int mt = 0; mt < 4; mt++) {
                int row = wm * 64 + mt * 16 + (lane & 15);
                ldsm4(af[mt][0], af[mt][1], af[mt][2], af[mt][3],
                      abase + sw128((uint32_t)(row * 128 + kb + (lane >> 4) * 16)));
            }
            // bh
            uint32_t bh[4][2];
            #pragma unroll
            for (int bt = 0; bt < 2; bt++) {
                int row = wn * 32 + bt * 16 + (lane & 7) + ((lane >> 4) & 1) * 8;
                int col = kb + (((lane >> 3) & 1) * 16);
                ldsm4(bh[2 * bt][0], bh[2 * bt][1], bh[2 * bt + 1][0], bh[2 * bt + 1][1],
                      bbase + sw128((uint32_t)(row * 128 + col)));
            }
            #pragma unroll
            for (int mt = 0; mt < 4; mt++)
                #pragma unroll
                for (int nt = 0; nt < 4; nt++)
                    mma16816(acc[mt][nt], af[mt], bh[nt]);
            // bl (reuse ah)
            uint32_t bl[4][2];
            #pragma unroll
            for (int bt = 0; bt < 2; bt++) {
                int row = wn * 32 + bt * 16 + (lane & 7) + ((lane >> 4) & 1) * 8;
                int col = 64 + kb + (((lane >> 3) & 1) * 16);
                ldsm4(bl[2 * bt][0], bl[2 * bt][1], bl[2 * bt + 1][0], bl[2 * bt + 1][1],
                      bbase + sw128((uint32_t)(row * 128 + col)));
            }
            #pragma unroll
            for (int mt = 0; mt < 4; mt++)
                #pragma unroll
                for (int nt = 0; nt < 4; nt++)
                    mma16816(acc[mt][nt], af[mt], bl[nt]);
            // al (reuse bh)
            #pragma unroll
            for (int mt = 0; mt < 4; mt++) {
                int row = wm * 64 + mt * 16 + (lane & 15);
                ldsm4(af[mt][0], af[mt][1], af[mt][2], af[mt][3],
                      abase + sw128((uint32_t)(row * 128 + 64 + kb + (lane >> 4) * 16)));
            }
            #pragma unroll
            for (int mt = 0; mt < 4; mt++)
                #pragma unroll
                for (int nt = 0; nt < 4; nt++)
                    mma16816(acc[mt][nt], af[mt], bh[nt]);
        }
        __syncthreads();
    }

    // ---- epilogue
    const int gid = lane >> 2;
    const int tid2 = lane & 3;
    if (mode == 1) {
        #pragma unroll
        for (int mt = 0; mt < 4; mt++) {
            int row0 = m0 + wm * 64 + mt * 16 + gid;
            #pragma unroll
            for (int nt = 0; nt < 4; nt++) {
                int ncol = n0 + wn * 32 + nt * 8 + tid2 * 2;
                *(float2*)(outp + (size_t)row0 * 1024 + ncol) =
                    make_float2(acc[mt][nt][0], acc[mt][nt][1]);
                *(float2*)(outp + (size_t)(row0 + 8) * 1024 + ncol) =
                    make_float2(acc[mt][nt][2], acc[mt][nt][3]);
            }
        }
        return;
    }
    // mode 0: split into per-head hi/lo panels
    #pragma unroll
    for (int mt = 0; mt < 4; mt++) {
        int row0 = m0 + wm * 64 + mt * 16 + gid;
        #pragma unroll
        for (int nt = 0; nt < 4; nt++) {
            int ncol = n0 + wn * 32 + nt * 8 + tid2 * 2;
            int which = ncol >> 10;          // 0=Q 1=K 2=V
            int c = ncol & 1023;
            int h = c >> 6, d = c & 63;
            __nv_bfloat16* hiA = (which == 0) ? g_Qh : (which == 1) ? g_Kh : g_Vh;
            __nv_bfloat16* loA = (which == 0) ? g_Ql : (which == 1) ? g_Kl : g_Vl;
            float sc = (which == 0) ? QSCALE : 1.0f;
            #pragma unroll
            for (int rr = 0; rr < 2; rr++) {
                int row = row0 + rr * 8;
                int b = row >> 11, t = row & 2047;
                size_t base = ((size_t)(b * NHEADS + h) * SEQ + t) * 64 + d;
                float v0 = acc[mt][nt][2 * rr] * sc;
                float v1 = acc[mt][nt][2 * rr + 1] * sc;
                __nv_bfloat16 h0, l0, h1, l1;
                split2(v0, h0, l0); split2(v1, h1, l1);
                *(__nv_bfloat162*)(hiA + base) = __nv_bfloat162(h0, h1);
                *(__nv_bfloat162*)(loA + base) = __nv_bfloat162(l0, l1);
            }
        }
    }
}

// ---------------------------------------------------------------------------
// 2-slot HMMA flash attention + exclusive output mod
// CTA: 128 q rows, 256 threads (8 warps x 16 rows). KV tile 64, 2 stages.
// Smem: Qh 16KB + Ql 16KB + 2 x 32KB = 96KB -> 2 CTAs/SM.
// ---------------------------------------------------------------------------
#define AQ (2 * 16384)           // 32768
#define AST 32768
#define ASMEM (AQ + 2 * AST)     // 98304
#define NKV (SEQ / 64)           // 32

__global__ void __launch_bounds__(256, 2)
attn_mma_kernel()
{
    extern __shared__ char smem[];
    const uint32_t sb = smem_u32(smem);
    const int tid = threadIdx.x;
    const int wid = tid >> 5;       // 0..7
    const int lane = tid & 31;
    const int bh = blockIdx.x;
    const int q0 = blockIdx.y * 128;
    const int b_ = bh >> 4, h_ = bh & 15;

    const __nv_bfloat16* Qhs = g_Qh + ((size_t)bh * SEQ + q0) * 64;
    const __nv_bfloat16* Qls = g_Ql + ((size_t)bh * SEQ + q0) * 64;
    const __nv_bfloat16* Khs = g_Kh + (size_t)bh * SEQ * 64;
    const __nv_bfloat16* Kls = g_Kl + (size_t)bh * SEQ * 64;
    const __nv_bfloat16* Vhs = g_Vh + (size_t)bh * SEQ * 64;
    const __nv_bfloat16* Vls = g_Vl + (size_t)bh * SEQ * 64;

    auto fillKV = [&](int stage, int kt) {
        uint32_t base = sb + AQ + stage * AST;
        int t0 = kt * 64;
        #pragma unroll
        for (int i = 0; i < 8; i++) {
            int g = i * 256 + tid;
            int seg = g >> 9, idx = g & 511;
            int row = idx >> 3, gr = idx & 7;
            const __nv_bfloat16* src =
                (seg == 0) ? Khs : (seg == 1) ? Kls : (seg == 2) ? Vhs : Vls;
            cp_async16(base + seg * 8192 + sw128((uint32_t)(row * 128 + gr * 16)),
                       src + (size_t)(t0 + row) * 64 + gr * 8);
        }
    };

    // G0: Q (2 panels x 128 rows x 8 granules = 2048) + kv0
    #pragma unroll
    for (int i = 0; i < 8; i++) {
        int g = i * 256 + tid;
        int panel = g >> 10, idx = g & 1023;
        int row = idx >> 3, gr = idx & 7;
        const __nv_bfloat16* src = (panel ? Qls : Qhs) + (size_t)row * 64 + gr * 8;
        cp_async16(sb + panel * 16384 + sw128((uint32_t)(row * 128 + gr * 16)), src);
    }
    fillKV(0, 0);
    cp_commit();
    fillKV(1, 1); cp_commit();

    float accO[8][4] = {};
    float m0 = -CUDART_INF_F, m1 = -CUDART_INF_F;
    float l0 = 0.0f, l1 = 0.0f;

    cp_wait1();                  // G0 (Q + kv0) complete
    __syncthreads();

    for (int kt = 0; kt < NKV; kt++) {
        const uint32_t kb = sb + AQ + (kt & 1) * AST;
        const uint32_t klb = kb + 8192;

        // ---- S = Qh*Kh + Qh*Kl + Ql*Kh
        float accS[8][4] = {};
        const int arow = wid * 16 + (lane & 15);
        #pragma unroll
        for (int s = 0; s < 4; s++) {
            const int cb = s * 32 + (lane >> 4) * 16;
            uint32_t ah[4], al[4];
            ldsm4(ah[0], ah[1], ah[2], ah[3], sb + sw128((uint32_t)(arow * 128 + cb)));
            ldsm4(al[0], al[1], al[2], al[3], sb + 16384 + sw128((uint32_t)(arow * 128 + cb)));
            #pragma unroll
            for (int nb = 0; nb < 4; nb++) {
                int row = nb * 16 + (lane & 7) + ((lane >> 4) & 1) * 8;
                int off = s * 32 + ((lane >> 3) & 1) * 16;
                uint32_t bhf[4], blf[4];
                ldsm4(bhf[0], bhf[1], bhf[2], bhf[3],
                      kb + sw128((uint32_t)(row * 128 + off)));
                ldsm4(blf[0], blf[1], blf[2], blf[3],
                      klb + sw128((uint32_t)(row * 128 + off)));
                mma16816(accS[2 * nb],     ah, &bhf[0]);
                mma16816(accS[2 * nb + 1], ah, &bhf[2]);
                mma16816(accS[2 * nb],     ah, &blf[0]);
                mma16816(accS[2 * nb + 1], ah, &blf[2]);
                mma16816(accS[2 * nb],     al, &bhf[0]);
                mma16816(accS[2 * nb + 1], al, &bhf[2]);
            }
        }

        // ---- online softmax (base-2)
        float mx0 = -CUDART_INF_F, mx1 = -CUDART_INF_F;
        #pragma unroll
        for (int nt = 0; nt < 8; nt++) {
            mx0 = fmaxf(mx0, fmaxf(accS[nt][0], accS[nt][1]));
            mx1 = fmaxf(mx1, fmaxf(accS[nt][2], accS[nt][3]));
        }
        mx0 = qmax(mx0); mx1 = qmax(mx1);
        float m0n = fmaxf(m0, mx0), m1n = fmaxf(m1, mx1);
        float c0 = ex2f(m0 - m0n), c1 = ex2f(m1 - m1n);
        m0 = m0n; m1 = m1n;
        float s0 = 0.0f, s1 = 0.0f;
        #pragma unroll
        for (int nt = 0; nt < 8; nt++) {
            accS[nt][0] = ex2f(accS[nt][0] - m0);
            accS[nt][1] = ex2f(accS[nt][1] - m0);
            accS[nt][2] = ex2f(accS[nt][2] - m1);
            accS[nt][3] = ex2f(accS[nt][3] - m1);
            s0 += accS[nt][0] + accS[nt][1];
            s1 += accS[nt][2] + accS[nt][3];
            accO[nt][0] *= c0; accO[nt][1] *= c0;
            accO[nt][2] *= c1; accO[nt][3] *= c1;
        }
        l0 = l0 * c0 + qsum(s0);
        l1 = l1 * c1 + qsum(s1);

        // ---- PV: Ph*Vh + Ph*Vl + Pl*Vh (natural A-frag packing)
        const uint32_t vhb = kb + 16384, vlb = kb + 24576;
        #pragma unroll
        for (int s = 0; s < 4; s++) {
            uint32_t aPh[4], aPl[4];
            #pragma unroll
            for (int half = 0; half < 2; half++) {
                const float* a = accS[2 * s + half];
                uint32_t ph0 = packbf(a[1], a[0]);
                uint32_t ph1 = packbf(a[3], a[2]);
                float pl0e = a[0] - __uint_as_float(ph0 << 16);
                float pl0o = a[1] - __uint_as_float(ph0 & 0xffff0000u);
                float pl1e = a[2] - __uint_as_float(ph1 << 16);
                float pl1o = a[3] - __uint_as_float(ph1 & 0xffff0000u);
                aPh[2 * half]     = ph0;
                aPh[2 * half + 1] = ph1;
                aPl[2 * half]     = packbf(pl0o, pl0e);
                aPl[2 * half + 1] = packbf(pl1o, pl1e);
            }
            int vrow = s * 16 + ((lane >> 3) & 1) * 8 + (lane & 7);
            #pragma unroll
            for (int j = 0; j < 4; j++) {
                int colb = (j * 16 + ((lane >> 4) & 1) * 8) * 2;
                uint32_t vh[4], vl[4];
                ldsm4t(vh[0], vh[1], vh[2], vh[3],
                       vhb + sw128((uint32_t)(vrow * 128 + colb)));
                ldsm4t(vl[0], vl[1], vl[2], vl[3],
                       vlb + sw128((uint32_t)(vrow * 128 + colb)));
                mma16816(accO[2 * j],     aPh, &vh[0]);
                mma16816(accO[2 * j + 1], aPh, &vh[2]);
                mma16816(accO[2 * j],     aPh, &vl[0]);
                mma16816(accO[2 * j + 1], aPh, &vl[2]);
                mma16816(accO[2 * j],     aPl, &vh[0]);
                mma16816(accO[2 * j + 1], aPl, &vh[2]);
            }
        }

        __syncthreads();
        if (kt + 2 < NKV) fillKV(kt & 1, kt + 2);
        cp_commit();
        cp_wait1();
        __syncthreads();
    }

    // ---- epilogue: normalize + exclusive output mod, write Z in 2-slot layout
    const float inv0 = 1.0f / l0, inv1 = 1.0f / l1;
    const int t_base = q0 + wid * 16 + (lane >> 2);
    const int dbase = (lane & 3) * 2;

    #pragma unroll
    for (int rs = 0; rs < 2; rs++) {
        int t = t_base + rs * 8;
        float inv = rs ? inv1 : inv0;
        float vv[8][2];
        float vsq = 0.0f, ydv = 0.0f, ysq = 0.0f;
        #pragma unroll
        for (int nt = 0; nt < 8; nt++) {
            size_t vb = ((size_t)bh * SEQ + t) * 64 + dbase + nt * 8;
            __nv_bfloat162 vh2 = *(const __nv_bfloat162*)(g_Vh + vb);
            __nv_bfloat162 vl2 = *(const __nv_bfloat162*)(g_Vl + vb);
            float vx = __bfloat162float(vh2.x) + __bfloat162float(vl2.x);
            float vy = __bfloat162float(vh2.y) + __bfloat162float(vl2.y);
            vv[nt][0] = vx; vv[nt][1] = vy;
            float y0 = accO[nt][2 * rs] * inv;
            float y1 = accO[nt][2 * rs + 1] * inv;
            accO[nt][2 * rs] = y0; accO[nt][2 * rs + 1] = y1;
            vsq = fmaf(vx, vx, fmaf(vy, vy, vsq));
            ydv = fmaf(y0, vx, fmaf(y1, vy, ydv));
            ysq = fmaf(y0, y0, fmaf(y1, y1, ysq));
        }
        vsq = qsum(vsq); ydv = qsum(ydv); ysq = qsum(ysq);
        float scale = (vsq > 0.0f) ? (ydv / fmaxf(vsq, FLT_MIN)) : 0.0f;
        float zsq = 0.0f;
        float zz[8][2];
        #pragma unroll
        for (int nt = 0; nt < 8; nt++) {
            float z0 = accO[nt][2 * rs] - scale * vv[nt][0];
            float z1 = accO[nt][2 * rs + 1] - scale * vv[nt][1];
            zz[nt][0] = z0; zz[nt][1] = z1;
            zsq = fmaf(z0, z0, fmaf(z1, z1, zsq));
        }
        zsq = qsum(zsq);
        float ref_norm = fmaxf(sqrtf(ysq), sqrtf(vsq));
        float tol = FLT_EPSILON * 64.0f * ref_norm;
        bool zero_out = (vsq > 0.0f) && (sqrtf(zsq) <= tol);
        size_t zrow = (size_t)(b_ * SEQ + t) * 2048;
        #pragma unroll
        for (int nt = 0; nt < 8; nt++) {
            float z0 = zero_out ? 0.0f : zz[nt][0];
            float z1 = zero_out ? 0.0f : zz[nt][1];
            int c = h_ * 64 + dbase + nt * 8;
            size_t o = zrow + (c >> 5) * 64 + (c & 31);
            __nv_bfloat16 h0, l0b, h1, l1b;
            split2(z0, h0, l0b); split2(z1, h1, l1b);
            *(__nv_bfloat162*)(g_Zs2 + o) = __nv_bfloat162(h0, h1);
            *(__nv_bfloat162*)(g_Zs2 + o + 32) = __nv_bfloat162(l0b, l1b);
        }
    }
}

// ---------------------------------------------------------------------------
extern "C" void kernel_launch(void* const* d_in, const int* in_sizes, int n_in,
                              void* d_out, int out_size)
{
    const float* x  = (const float*)d_in[0];
    const float* Wq = (const float*)d_in[1];
    const float* Wk = (const float*)d_in[2];
    const float* Wv = (const float*)d_in[3];
    const float* Wo = (const float*)d_in[4];
    float* out = (float*)d_out;

    cudaFuncSetAttribute(gemm2s_kernel, cudaFuncAttributeMaxDynamicSharedMemorySize, GSMEM);
    cudaFuncSetAttribute(attn_mma_kernel, cudaFuncAttributeMaxDynamicSharedMemorySize, ASMEM);

    convX_kernel<<<(ROWS * D_MODEL + 255) / 256, 256>>>(x);
    dim3 gw((D_MODEL * D_MODEL + 255) / 256, 4);
    convW_kernel<<<gw, 256>>>(Wq, Wk, Wv, Wo);

    // fused QKV projection -> per-head hi/lo panels
    dim3 gqkv(3 * D_MODEL / BNg, ROWS / BMg);   // (24, 32)
    gemm2s_kernel<<<gqkv, 256, GSMEM>>>(nullptr, 0);

    // attention (writes g_Zs2 directly)
    dim3 gattn(NBH, SEQ / 128);                 // (32, 16)
    attn_mma_kernel<<<gattn, 256, ASMEM>>>();

    // output projection
    dim3 gout(D_MODEL / BNg, ROWS / BMg);       // (8, 32)
    gemm2s_kernel<<<gout, 256, GSMEM>>>(out, 1);
}